// round 14
// baseline (speedup 1.0000x reference)
#include <cuda_runtime.h>
#include <cuda_fp16.h>
#include <math.h>
#include <stdint.h>

#define B_   2
#define T_   2048
#define D_   512
#define H_   8
#define HD_  64
#define F_   2048
#define M_   (B_*T_)
#define CH_  64
#define NCH_ (T_/CH_)
#define NBH_ (B_*H_)
#define QKVO (NBH_*T_*HD_)

// ------------------------- scratch globals ---------------------------------
__device__ __half g_xnh[M_*D_], g_xnl[M_*D_];
__device__ __half g_ath[M_*D_], g_atl[M_*D_];
__device__ __half g_h2h[M_*D_], g_h2l[M_*D_];
__device__ __half g_f1h[M_*F_], g_f1l[M_*F_];
__device__ __half g_wqkvh[3*D_*D_];          // Wq|Wk|Wv rows (hi only)
__device__ __half g_woh[D_*D_];
__device__ __half g_w1h[F_*D_];
__device__ __half g_w2h[D_*F_];
__device__ float g_QKV[3*QKVO];              // Q|K|V [b,h,t,e]
__device__ float g_x2[M_*D_];
__device__ float g_Schk[2*NBH_*NCH_*HD_*HD_];
__device__ float g_zchk[2*NBH_*NCH_*HD_];
__device__ float g_U   [2*NBH_*NCH_*HD_*HD_];
__device__ float g_zU  [2*NBH_*NCH_*HD_];

// ------------------------- helpers -----------------------------------------
static __device__ __forceinline__ uint32_t stou(const void* p){
    uint32_t a;
    asm("{ .reg .u64 t; cvta.to.shared.u64 t, %1; cvt.u32.u64 %0, t; }" : "=r"(a) : "l"(p));
    return a;
}
static __device__ __forceinline__ void cp16(uint32_t dst, const void* src){
    asm volatile("cp.async.cg.shared.global [%0], [%1], 16;" :: "r"(dst), "l"(src));
}
static __device__ __forceinline__ void ldm4(uint32_t* a, uint32_t addr){
    asm volatile("ldmatrix.sync.aligned.m8n8.x4.shared.b16 {%0,%1,%2,%3}, [%4];"
        : "=r"(a[0]),"=r"(a[1]),"=r"(a[2]),"=r"(a[3]) : "r"(addr));
}
static __device__ __forceinline__ void ldm2(uint32_t* b, uint32_t addr){
    asm volatile("ldmatrix.sync.aligned.m8n8.x2.shared.b16 {%0,%1}, [%2];"
        : "=r"(b[0]),"=r"(b[1]) : "r"(addr));
}
static __device__ __forceinline__ void mma16816(float* c, const uint32_t* a, const uint32_t* b){
    asm volatile("mma.sync.aligned.m16n8k16.row.col.f32.f16.f16.f32 "
        "{%0,%1,%2,%3}, {%4,%5,%6,%7}, {%8,%9}, {%0,%1,%2,%3};"
        : "+f"(c[0]),"+f"(c[1]),"+f"(c[2]),"+f"(c[3])
        : "r"(a[0]),"r"(a[1]),"r"(a[2]),"r"(a[3]), "r"(b[0]),"r"(b[1]));
}
static __device__ __forceinline__ uint32_t pack2h(float a, float b, float* la, float* lb){
    __half ha = __float2half(a), hb = __float2half(b);
    *la = a - __half2float(ha);
    *lb = b - __half2float(hb);
    return (uint32_t)__half_as_ushort(ha) | ((uint32_t)__half_as_ushort(hb) << 16);
}
static __device__ __forceinline__ uint32_t pack2l(float la, float lb){
    return (uint32_t)__half_as_ushort(__float2half(la)) |
           ((uint32_t)__half_as_ushort(__float2half(lb)) << 16);
}

#define ROWB  144
#define ATILE 18432
#define STGB  36864
#define GEMM_SMEM (2*STGB)
#define BOFF64  9216
#define STGB64  27648
#define GEMM64_SMEM (2*STGB64)

// ---------------------------------------------------------------------------
// 128x128 split-fp16 GEMM, 4 warps, warp tile 64x64, 2-stage, 3 CTAs/SM.
// K'=2K: passes (Ah,Bh),(Al,Bh).
// MODE: 3=bias+gelu->split fp16   4=fused QKV scatter (elu for n<1024)
// ---------------------------------------------------------------------------
template<int MODE, int KDIM>
__global__ void __launch_bounds__(128,3) tc_gemm_w64(
    const __half* __restrict__ Ah, const __half* __restrict__ Al,
    const __half* __restrict__ Bh,
    int N, const float* __restrict__ bias,
    float* __restrict__ outF,
    __half* __restrict__ outH, __half* __restrict__ outL)
{
    extern __shared__ char dyns[];
    uint32_t sb = stou(dyns);

    int tid = threadIdx.x;
    int lane = tid & 31, w = tid >> 5;
    int warp_m = w >> 1, warp_n = w & 1;       // 2 x 2 warps, 64x64 each
    int m0 = blockIdx.y * 128;
    int n0 = blockIdx.x * 128;

    float acc[4][8][4];
#pragma unroll
    for (int i=0;i<4;i++)
#pragma unroll
        for (int j=0;j<8;j++)
#pragma unroll
            for (int k=0;k<4;k++) acc[i][j][k] = 0.f;

    const int NIT = 2*KDIM/64;

    auto fill = [&](int itf){
        int st = itf & 1;
        int kp = itf * 64;
        int pass = kp / KDIM;
        int koff = kp - pass*KDIM;
        const __half* pA = pass ? Al : Ah;
        uint32_t base = sb + st*STGB;
#pragma unroll
        for (int i=0;i<16;i++){
            int q = tid + i*128;               // 0..2047
            int isB = q >> 10;
            int r   = (q >> 3) & 127;
            int c16 = q & 7;
            const __half* src =
                (isB ? (Bh + (size_t)(n0+r)*KDIM) : (pA + (size_t)(m0+r)*KDIM)) + koff + c16*8;
            cp16(base + isB*ATILE + r*ROWB + c16*16, src);
        }
        asm volatile("cp.async.commit_group;" ::: "memory");
    };

    // A frags: 16 rows x 2 k-halves per x4 call
    uint32_t aBase = (uint32_t)((warp_m*64 + (lane & 15))*ROWB + ((lane >> 4) << 4));
    // B frags x4: covers 2 n-tiles (nt pair) x 2 k-halves
    uint32_t bBase = (uint32_t)(ATILE +
        (warp_n*64 + ((lane >> 4) << 3) + (lane & 7))*ROWB + (((lane >> 3) & 1) << 4));

    fill(0);
    for (int it=0; it<NIT; ++it){
        if (it+1 < NIT){
            fill(it+1);
            asm volatile("cp.async.wait_group 1;" ::: "memory");
        } else {
            asm volatile("cp.async.wait_group 0;" ::: "memory");
        }
        __syncthreads();
        uint32_t stg = sb + (it&1)*STGB;
#pragma unroll
        for (int kk=0; kk<64; kk+=16){
            uint32_t afrag[4][4], bfrag[8][2];
#pragma unroll
            for (int mt=0;mt<4;mt++) ldm4(afrag[mt], stg + aBase + mt*(16*ROWB) + kk*2);
#pragma unroll
            for (int p=0;p<4;p++){
                uint32_t r4[4];
                ldm4(r4, stg + bBase + p*(16*ROWB) + kk*2);
                bfrag[2*p][0]=r4[0]; bfrag[2*p][1]=r4[1];
                bfrag[2*p+1][0]=r4[2]; bfrag[2*p+1][1]=r4[3];
            }
#pragma unroll
            for (int mt=0;mt<4;mt++)
#pragma unroll
                for (int nt=0;nt<8;nt++) mma16816(acc[mt][nt], afrag[mt], bfrag[nt]);
        }
        __syncthreads();
    }

    int mb = m0 + warp_m*64;
    int nb = n0 + warp_n*64;
#pragma unroll
    for (int mt=0; mt<4; mt++){
#pragma unroll
        for (int half=0; half<2; half++){
            int m = mb + mt*16 + (lane>>2) + half*8;
            int bb = m >> 11, tt = m & (T_-1);
#pragma unroll
            for (int nt=0; nt<8; nt++){
                int n = nb + nt*8 + (lane&3)*2;
                float v0 = acc[mt][nt][half*2];
                float v1 = acc[mt][nt][half*2+1];
                if (MODE == 4){
                    int mat = n >> 9;              // 0=Q 1=K 2=V
                    if (mat < 2){
                        v0 = v0>0.f ? v0+1.f : expf(v0);
                        v1 = v1>0.f ? v1+1.f : expf(v1);
                    }
                    int hh = (n >> 6) & 7, ee = n & 63;
                    float* dst = outF + (size_t)mat*QKVO
                               + ((((size_t)(bb*H_ + hh))*T_ + tt)<<6) + ee;
                    float2 o; o.x=v0; o.y=v1;
                    *(float2*)dst = o;
                } else {   // MODE 3: bias + exact GELU -> split fp16
                    size_t idx = (size_t)m*N + n;
                    float a = v0 + bias[n];
                    float b = v1 + bias[n+1];
                    a = 0.5f*a*(1.f+erff(a*0.70710678118654752f));
                    b = 0.5f*b*(1.f+erff(b*0.70710678118654752f));
                    float la, lb;
                    uint32_t hp = pack2h(a, b, &la, &lb);
                    uint32_t lp = pack2l(la, lb);
                    *(uint32_t*)(outH + idx) = hp;
                    *(uint32_t*)(outL + idx) = lp;
                }
            }
        }
    }
}

// ---------------------------------------------------------------------------
// 64x128 split-fp16 GEMM, 2-stage, 3 CTAs/SM (validated R13). bias+res->fp32.
// ---------------------------------------------------------------------------
template<int KDIM>
__global__ void __launch_bounds__(256,3) tc_gemm64(
    const __half* __restrict__ Ah, const __half* __restrict__ Al,
    const __half* __restrict__ Bh,
    int N, const float* __restrict__ bias, const float* __restrict__ res,
    float* __restrict__ outF)
{
    extern __shared__ char dyns[];
    uint32_t sb = stou(dyns);

    int tid = threadIdx.x;
    int lane = tid & 31, w = tid >> 5;
    int warp_m = w >> 2, warp_n = w & 3;
    int m0 = blockIdx.y * 64;
    int n0 = blockIdx.x * 128;

    float acc[2][4][4];
#pragma unroll
    for (int i=0;i<2;i++)
#pragma unroll
        for (int j=0;j<4;j++)
#pragma unroll
            for (int k=0;k<4;k++) acc[i][j][k] = 0.f;

    const int NIT = 2*KDIM/64;

    auto fill = [&](int itf){
        int st = itf & 1;
        int kp = itf * 64;
        int pass = kp / KDIM;
        int koff = kp - pass*KDIM;
        const __half* pA = pass ? Al : Ah;
        uint32_t base = sb + st*STGB64;
#pragma unroll
        for (int i=0;i<6;i++){
            int q = tid + i*256;
            if (q < 512){
                int r = q >> 3, c16 = q & 7;
                cp16(base + r*ROWB + c16*16,
                     pA + (size_t)(m0+r)*KDIM + koff + c16*8);
            } else {
                int q2 = q - 512;
                int r = q2 >> 3, c16 = q2 & 7;
                cp16(base + BOFF64 + r*ROWB + c16*16,
                     Bh + (size_t)(n0+r)*KDIM + koff + c16*8);
            }
        }
        asm volatile("cp.async.commit_group;" ::: "memory");
    };

    uint32_t aBase = (uint32_t)((warp_m*32 + (lane & 15))*ROWB + ((lane >> 4) << 4));
    uint32_t bBase = (uint32_t)(BOFF64 + (warp_n*32 + (lane & 7))*ROWB + (((lane >> 3) & 1) << 4));

    fill(0);
    for (int it=0; it<NIT; ++it){
        if (it+1 < NIT){
            fill(it+1);
            asm volatile("cp.async.wait_group 1;" ::: "memory");
        } else {
            asm volatile("cp.async.wait_group 0;" ::: "memory");
        }
        __syncthreads();
        uint32_t stg = sb + (it&1)*STGB64;
#pragma unroll
        for (int kk=0; kk<64; kk+=16){
            uint32_t afrag[2][4], bfrag[4][2];
#pragma unroll
            for (int mt=0;mt<2;mt++) ldm4(afrag[mt], stg + aBase + mt*(16*ROWB) + kk*2);
#pragma unroll
            for (int nt=0;nt<4;nt++) ldm2(bfrag[nt], stg + bBase + nt*(8*ROWB) + kk*2);
#pragma unroll
            for (int mt=0;mt<2;mt++)
#pragma unroll
                for (int nt=0;nt<4;nt++) mma16816(acc[mt][nt], afrag[mt], bfrag[nt]);
        }
        __syncthreads();
    }

    int mb = m0 + warp_m*32;
    int nb = n0 + warp_n*32;
#pragma unroll
    for (int mt=0; mt<2; mt++){
#pragma unroll
        for (int half=0; half<2; half++){
            int m = mb + mt*16 + (lane>>2) + half*8;
#pragma unroll
            for (int nt=0; nt<4; nt++){
                int n = nb + nt*8 + (lane&3)*2;
                float v0 = acc[mt][nt][half*2];
                float v1 = acc[mt][nt][half*2+1];
                size_t idx = (size_t)m*N + n;
                float2 rv = *(const float2*)(res + idx);
                float2 o;
                o.x = v0 + bias[n]   + rv.x;
                o.y = v1 + bias[n+1] + rv.y;
                *(float2*)(outF + idx) = o;
            }
        }
    }
}

// ------------------------- batched weight split (hi only, vectorized) -------
__global__ void __launch_bounds__(256) split_all_kernel(
    const float* __restrict__ Wq, const float* __restrict__ Wk,
    const float* __restrict__ Wv, const float* __restrict__ Wo,
    const float* __restrict__ W1, const float* __restrict__ W2)
{
    int g = blockIdx.x * 256 + threadIdx.x;
    const float* src; __half* dh;
    if (g < 196608){
        int which = g >> 16;
        int j = g & 65535;
        src = (which==0 ? Wq : which==1 ? Wk : Wv) + j*4;
        dh = g_wqkvh + ((size_t)which << 18) + j*4;
    } else if (g < 262144){
        int j = g - 196608; src = Wo + (size_t)j*4; dh = g_woh + (size_t)j*4;
    } else if (g < 524288){
        int j = g - 262144; src = W1 + (size_t)j*4; dh = g_w1h + (size_t)j*4;
    } else {
        int j = g - 524288; src = W2 + (size_t)j*4; dh = g_w2h + (size_t)j*4;
    }
    float4 v = *(const float4*)src;
    uint2 hp;
    hp.x = (uint32_t)__half_as_ushort(__float2half(v.x)) |
           ((uint32_t)__half_as_ushort(__float2half(v.y)) << 16);
    hp.y = (uint32_t)__half_as_ushort(__float2half(v.z)) |
           ((uint32_t)__half_as_ushort(__float2half(v.w)) << 16);
    *(uint2*)dh = hp;
}

// ------------------------- LayerNorm + fp16 split ---------------------------
__global__ void __launch_bounds__(256) ln_split_kernel(
    const float* __restrict__ x, const float* __restrict__ g,
    const float* __restrict__ b, __half* __restrict__ yh,
    __half* __restrict__ yl)
{
    int row = blockIdx.x;
    const float* xr = x + (size_t)row * D_;
    int tid = threadIdx.x;
    float v0 = xr[tid], v1 = xr[tid + 256];
    float s  = v0 + v1, ss = v0*v0 + v1*v1;
    __shared__ float sh[16];
#pragma unroll
    for (int o = 16; o; o >>= 1) {
        s  += __shfl_xor_sync(0xffffffffu, s,  o);
        ss += __shfl_xor_sync(0xffffffffu, ss, o);
    }
    int w = tid >> 5;
    if ((tid & 31) == 0) { sh[w] = s; sh[w + 8] = ss; }
    __syncthreads();
    float S = 0.f, SS = 0.f;
#pragma unroll
    for (int i = 0; i < 8; i++) { S += sh[i]; SS += sh[8 + i]; }
    float mean = S * (1.0f / D_);
    float rstd = rsqrtf(SS * (1.0f / D_) - mean*mean + 1e-5f);
    size_t base = (size_t)row * D_;
    float o0 = (v0 - mean) * rstd * g[tid]       + b[tid];
    float o1 = (v1 - mean) * rstd * g[tid + 256] + b[tid + 256];
    __half h0 = __float2half(o0), h1 = __float2half(o1);
    yh[base + tid]       = h0;
    yh[base + tid + 256] = h1;
    yl[base + tid]       = __float2half(o0 - __half2float(h0));
    yl[base + tid + 256] = __float2half(o1 - __half2float(h1));
}

// ---------------------------------------------------------------------------
// Scan level 1 (DUAL direction) — validated R12, unchanged
// ---------------------------------------------------------------------------
__global__ void __launch_bounds__(256) usum_dual_kernel(const float* __restrict__ dlogit)
{
    int bx  = blockIdx.x;
    int j   = bx & 31;
    int bh  = bx >> 5;
    int h   = bh & 7;
    float lam = 1.f / (1.f + expf(-dlogit[h]));

    __shared__ float sK[CH_ * HD_];
    __shared__ float sV[CH_ * HD_];
    __shared__ float wf[CH_], wb[CH_];

    int tid = threadIdx.x;
    if (tid < CH_){
        wf[tid] = powf(lam, (float)(CH_ - 1 - tid));
        wb[tid] = powf(lam, (float)tid);
    }

    int lrow = tid >> 2;
    int lseg = (tid & 3) * 16;
    int pt = j * CH_ + lrow;
    const float* Kg = g_QKV + QKVO     + (size_t)bh * T_ * HD_;
    const float* Vg = g_QKV + 2*QKVO   + (size_t)bh * T_ * HD_;
    {
        const float4* kr = (const float4*)(Kg + (size_t)pt * HD_ + lseg);
        const float4* vr = (const float4*)(Vg + (size_t)pt * HD_ + lseg);
        float4* sk = (float4*)(sK + lrow * HD_ + lseg);
        float4* sv = (float4*)(sV + lrow * HD_ + lseg);
        sk[0]=kr[0]; sk[1]=kr[1]; sk[2]=kr[2]; sk[3]=kr[3];
        sv[0]=vr[0]; sv[1]=vr[1]; sv[2]=vr[2]; sv[3]=vr[3];
    }
    __syncthreads();

    int d = tid & 63, c = tid >> 6;
    int e0 = c * 16;
    float aF[16], aB[16];
#pragma unroll
    for (int i = 0; i < 16; i++){ aF[i] = 0.f; aB[i] = 0.f; }
    float zF = 0.f, zB = 0.f;

#pragma unroll 4
    for (int s = 0; s < CH_; s++){
        float kr = sK[s * HD_ + d];
        float kf = kr * wf[s];
        float kb = kr * wb[s];
        zF += kf; zB += kb;
        const float4* vv = (const float4*)(sV + s * HD_ + e0);
        float4 a0 = vv[0], a1 = vv[1], a2 = vv[2], a3 = vv[3];
        aF[0]=fmaf(kf,a0.x,aF[0]); aB[0]=fmaf(kb,a0.x,aB[0]);
        aF[1]=fmaf(kf,a0.y,aF[1]); aB[1]=fmaf(kb,a0.y,aB[1]);
        aF[2]=fmaf(kf,a0.z,aF[2]); aB[2]=fmaf(kb,a0.z,aB[2]);
        aF[3]=fmaf(kf,a0.w,aF[3]); aB[3]=fmaf(kb,a0.w,aB[3]);
        aF[4]=fmaf(kf,a1.x,aF[4]); aB[4]=fmaf(kb,a1.x,aB[4]);
        aF[5]=fmaf(kf,a1.y,aF[5]); aB[5]=fmaf(kb,a1.y,aB[5]);
        aF[6]=fmaf(kf,a1.z,aF[6]); aB[6]=fmaf(kb,a1.z,aB[6]);
        aF[7]=fmaf(kf,a1.w,aF[7]); aB[7]=fmaf(kb,a1.w,aB[7]);
        aF[8]=fmaf(kf,a2.x,aF[8]); aB[8]=fmaf(kb,a2.x,aB[8]);
        aF[9]=fmaf(kf,a2.y,aF[9]); aB[9]=fmaf(kb,a2.y,aB[9]);
        aF[10]=fmaf(kf,a2.z,aF[10]); aB[10]=fmaf(kb,a2.z,aB[10]);
        aF[11]=fmaf(kf,a2.w,aF[11]); aB[11]=fmaf(kb,a2.w,aB[11]);
        aF[12]=fmaf(kf,a3.x,aF[12]); aB[12]=fmaf(kb,a3.x,aB[12]);
        aF[13]=fmaf(kf,a3.y,aF[13]); aB[13]=fmaf(kb,a3.y,aB[13]);
        aF[14]=fmaf(kf,a3.z,aF[14]); aB[14]=fmaf(kb,a3.z,aB[14]);
        aF[15]=fmaf(kf,a3.w,aF[15]); aB[15]=fmaf(kb,a3.w,aB[15]);
    }

    float* Uf = g_U + (size_t)((0 * NBH_ + bh) * NCH_ + j) * (HD_ * HD_);
    float* Ub = g_U + (size_t)((1 * NBH_ + bh) * NCH_ + (NCH_ - 1 - j)) * (HD_ * HD_);
#pragma unroll
    for (int i = 0; i < 16; i++){
        Uf[(e0 + i) * 64 + d] = aF[i];
        Ub[(e0 + i) * 64 + d] = aB[i];
    }
    if (c == 0){
        g_zU[(size_t)((0 * NBH_ + bh) * NCH_ + j) * HD_ + d] = zF;
        g_zU[(size_t)((1 * NBH_ + bh) * NCH_ + (NCH_ - 1 - j)) * HD_ + d] = zB;
    }
}

// ---------------------------------------------------------------------------
// Scan level 2: sweep — validated, unchanged
// ---------------------------------------------------------------------------
__global__ void __launch_bounds__(256) sweep_kernel(const float* __restrict__ dlogit)
{
    int bx  = blockIdx.x;
    int seg = bx & 15;
    int bh  = (bx >> 4) & 15;
    int dir = bx >> 8;
    int h   = bh & 7;
    float lam  = 1.f / (1.f + expf(-dlogit[h]));
    float lamC = powf(lam, (float)CH_);

    int el = seg * 256 + threadIdx.x;
    size_t base = (size_t)((dir * NBH_ + bh) * NCH_) * (HD_ * HD_);
    float S = 0.f;
#pragma unroll
    for (int jj = 0; jj < NCH_; jj++){
        size_t o = base + (size_t)jj * (HD_ * HD_) + el;
        float u = g_U[o];
        g_Schk[o] = S;
        S = fmaf(lamC, S, u);
    }
    if (seg == 0 && threadIdx.x < HD_){
        int d = threadIdx.x;
        size_t zb = (size_t)((dir * NBH_ + bh) * NCH_) * HD_;
        float z = 0.f;
#pragma unroll
        for (int jj = 0; jj < NCH_; jj++){
            float zu = g_zU[zb + jj * HD_ + d];
            g_zchk[zb + jj * HD_ + d] = z;
            z = fmaf(lamC, z, zu);
        }
    }
}

// ---------------------------------------------------------------------------
// Combined dual-direction chunk kernel — validated R12/R13, unchanged
// ---------------------------------------------------------------------------
#define COFF_Q   0
#define COFF_K   4160
#define COFF_P   8320
#define COFF_V   12480
#define COFF_SF  16576
#define COFF_SB  20928
#define COFF_ZF  25280
#define COFF_ZB  25344
#define COFF_LP  25408
#define CC_SMEM_BYTES ((25408 + 80) * 4)

__global__ void __launch_bounds__(256) chunk_comb_kernel(const float* __restrict__ dlogit)
{
    extern __shared__ float sm[];
    float* sQ  = sm + COFF_Q;
    float* sK  = sm + COFF_K;
    float* sP  = sm + COFF_P;
    float* sV  = sm + COFF_V;
    float* sSf = sm + COFF_SF;
    float* sSb = sm + COFF_SB;
    float* szf = sm + COFF_ZF;
    float* szb = sm + COFF_ZB;
    float* slp = sm + COFF_LP;

    int bx  = blockIdx.x;
    int j   = bx & 31;
    int bh  = bx >> 5;
    int h   = bh & 7;
    float lam = 1.f / (1.f + expf(-dlogit[h]));

    int tid = threadIdx.x;
    if (tid <= CH_) slp[tid] = powf(lam, (float)tid);

    const float* Qg  = g_QKV            + (size_t)bh * T_ * HD_;
    const float* Kg  = g_QKV + QKVO     + (size_t)bh * T_ * HD_;
    const float* Vg  = g_QKV + 2*QKVO   + (size_t)bh * T_ * HD_;
    const float* Sfin = g_Schk + (size_t)((0 * NBH_ + bh) * NCH_ + j) * (HD_ * HD_);
    const float* Sbin = g_Schk + (size_t)((1 * NBH_ + bh) * NCH_ + (NCH_ - 1 - j)) * (HD_ * HD_);
    const float* zfin = g_zchk + (size_t)((0 * NBH_ + bh) * NCH_ + j) * HD_;
    const float* zbin = g_zchk + (size_t)((1 * NBH_ + bh) * NCH_ + (NCH_ - 1 - j)) * HD_;

    int lrow = tid >> 2;
    int lseg = (tid & 3) * 16;
    int pt0 = j * CH_ + lrow;

#pragma unroll 4
    for (int i = 0; i < 16; i++) {
        sQ[lrow * 65 + lseg + i] = Qg[(size_t)pt0 * HD_ + lseg + i];
        sK[lrow * 65 + lseg + i] = Kg[(size_t)pt0 * HD_ + lseg + i];
    }
    {
        float4* svr = (float4*)(sV + lrow * 64 + lseg);
        const float4* vr = (const float4*)(Vg + (size_t)pt0 * HD_ + lseg);
        svr[0]=vr[0]; svr[1]=vr[1]; svr[2]=vr[2]; svr[3]=vr[3];
    }
#pragma unroll 4
    for (int i = 0; i < 16; i++) {
        int idx = tid * 16 + i;
        int e = idx >> 6, dd = idx & 63;
        sSf[dd * 68 + e] = Sfin[idx];
        sSb[dd * 68 + e] = Sbin[idx];
    }
    if (tid < 64){ szf[tid] = zfin[tid]; szb[tid] = zbin[tid]; }
    __syncthreads();

    {
        int ty = tid >> 4, tx = tid & 15;
        int r0 = ty * 4, c0 = tx * 4;
        float acc[4][4];
#pragma unroll
        for (int i = 0; i < 4; i++)
#pragma unroll
            for (int jc = 0; jc < 4; jc++) acc[i][jc] = 0.f;

        for (int d = 0; d < 64; d++) {
            float q0 = sQ[(r0+0)*65+d], q1 = sQ[(r0+1)*65+d];
            float q2 = sQ[(r0+2)*65+d], q3 = sQ[(r0+3)*65+d];
            float k0 = sK[(c0+0)*65+d], k1 = sK[(c0+1)*65+d];
            float k2 = sK[(c0+2)*65+d], k3 = sK[(c0+3)*65+d];
            acc[0][0]=fmaf(q0,k0,acc[0][0]); acc[0][1]=fmaf(q0,k1,acc[0][1]);
            acc[0][2]=fmaf(q0,k2,acc[0][2]); acc[0][3]=fmaf(q0,k3,acc[0][3]);
            acc[1][0]=fmaf(q1,k0,acc[1][0]); acc[1][1]=fmaf(q1,k1,acc[1][1]);
            acc[1][2]=fmaf(q1,k2,acc[1][2]); acc[1][3]=fmaf(q1,k3,acc[1][3]);
            acc[2][0]=fmaf(q2,k0,acc[2][0]); acc[2][1]=fmaf(q2,k1,acc[2][1]);
            acc[2][2]=fmaf(q2,k2,acc[2][2]); acc[2][3]=fmaf(q2,k3,acc[2][3]);
            acc[3][0]=fmaf(q3,k0,acc[3][0]); acc[3][1]=fmaf(q3,k1,acc[3][1]);
            acc[3][2]=fmaf(q3,k2,acc[3][2]); acc[3][3]=fmaf(q3,k3,acc[3][3]);
        }
#pragma unroll
        for (int i = 0; i < 4; i++) {
            int r = r0 + i;
#pragma unroll
            for (int jc = 0; jc < 4; jc++) {
                int cc = c0 + jc;
                int dlt = r >= cc ? r - cc : cc - r;
                sP[r * 65 + cc] = acc[i][jc] * slp[dlt];
            }
        }
    }
    __syncthreads();

    {
        int rr = (tid >> 3) * 2;
        int c0 = (tid & 7) * 8;
        float aA[2][8], aIf[2][8], aIb[2][8];
#pragma unroll
        for (int i = 0; i < 2; i++)
#pragma unroll
            for (int jc = 0; jc < 8; jc++){ aA[i][jc]=0.f; aIf[i][jc]=0.f; aIb[i][jc]=0.f; }
        float cs0 = 0.f, cs1 = 0.f;
        float cqf0 = 0.f, cqf1 = 0.f, cqb0 = 0.f, cqb1 = 0.f;

        for (int s = 0; s < 64; s++) {
            float a0 = sP[rr * 65 + s];
            float a1 = sP[(rr + 1) * 65 + s];
            cs0 += a0; cs1 += a1;
            float4 v0 = *(const float4*)(sV + s * 64 + c0);
            float4 v1 = *(const float4*)(sV + s * 64 + c0 + 4);
            aA[0][0]=fmaf(a0,v0.x,aA[0][0]); aA[0][1]=fmaf(a0,v0.y,aA[0][1]);
            aA[0][2]=fmaf(a0,v0.z,aA[0][2]); aA[0][3]=fmaf(a0,v0.w,aA[0][3]);
            aA[0][4]=fmaf(a0,v1.x,aA[0][4]); aA[0][5]=fmaf(a0,v1.y,aA[0][5]);
            aA[0][6]=fmaf(a0,v1.z,aA[0][6]); aA[0][7]=fmaf(a0,v1.w,aA[0][7]);
            aA[1][0]=fmaf(a1,v0.x,aA[1][0]); aA[1][1]=fmaf(a1,v0.y,aA[1][1]);
            aA[1][2]=fmaf(a1,v0.z,aA[1][2]); aA[1][3]=fmaf(a1,v0.w,aA[1][3]);
            aA[1][4]=fmaf(a1,v1.x,aA[1][4]); aA[1][5]=fmaf(a1,v1.y,aA[1][5]);
            aA[1][6]=fmaf(a1,v1.z,aA[1][6]); aA[1][7]=fmaf(a1,v1.w,aA[1][7]);
        }
        for (int d = 0; d < 64; d++) {
            float q0 = sQ[rr * 65 + d];
            float q1 = sQ[(rr + 1) * 65 + d];
            cqf0 = fmaf(q0, szf[d], cqf0);
            cqf1 = fmaf(q1, szf[d], cqf1);
            cqb0 = fmaf(q0, szb[d], cqb0);
            cqb1 = fmaf(q1, szb[d], cqb1);
            float4 f0 = *(const float4*)(sSf + d * 68 + c0);
            float4 f1 = *(const float4*)(sSf + d * 68 + c0 + 4);
            float4 b0 = *(const float4*)(sSb + d * 68 + c0);
            float4 b1 = *(const float4*)(sSb + d * 68 + c0 + 4);
            aIf[0][0]=fmaf(q0,f0.x,aIf[0][0]); aIf[0][1]=fmaf(q0,f0.y,aIf[0][1]);
            aIf[0][2]=fmaf(q0,f0.z,aIf[0][2]); aIf[0][3]=fmaf(q0,f0.w,aIf[0][3]);
            aIf[0][4]=fmaf(q0,f1.x,aIf[0][4]); aIf[0][5]=fmaf(q0,f1.y,aIf[0][5]);
            aIf[0][6]=fmaf(q0,f1.z,aIf[0][6]); aIf[0][7]=fmaf(q0,f1.w,aIf[0][7]);
            aIf[1][0]=fmaf(q1,f0.x,aIf[1][0]); aIf[1][1]=fmaf(q1,f0.y,aIf[1][1]);
            aIf[1][2]=fmaf(q1,f0.z,aIf[1][2]); aIf[1][3]=fmaf(q1,f0.w,aIf[1][3]);
            aIf[1][4]=fmaf(q1,f1.x,aIf[1][4]); aIf[1][5]=fmaf(q1,f1.y,aIf[1][5]);
            aIf[1][6]=fmaf(q1,f1.z,aIf[1][6]); aIf[1][7]=fmaf(q1,f1.w,aIf[1][7]);
            aIb[0][0]=fmaf(q0,b0.x,aIb[0][0]); aIb[0][1]=fmaf(q0,b0.y,aIb[0][1]);
            aIb[0][2]=fmaf(q0,b0.z,aIb[0][2]); aIb[0][3]=fmaf(q0,b0.w,aIb[0][3]);
            aIb[0][4]=fmaf(q0,b1.x,aIb[0][4]); aIb[0][5]=fmaf(q0,b1.y,aIb[0][5]);
            aIb[0][6]=fmaf(q0,b1.z,aIb[0][6]); aIb[0][7]=fmaf(q0,b1.w,aIb[0][7]);
            aIb[1][0]=fmaf(q1,b0.x,aIb[1][0]); aIb[1][1]=fmaf(q1,b0.y,aIb[1][1]);
            aIb[1][2]=fmaf(q1,b0.z,aIb[1][2]); aIb[1][3]=fmaf(q1,b0.w,aIb[1][3]);
            aIb[1][4]=fmaf(q1,b1.x,aIb[1][4]); aIb[1][5]=fmaf(q1,b1.y,aIb[1][5]);
            aIb[1][6]=fmaf(q1,b1.z,aIb[1][6]); aIb[1][7]=fmaf(q1,b1.w,aIb[1][7]);
        }

        int b = bh >> 3;
#pragma unroll
        for (int i = 0; i < 2; i++) {
            int r = rr + i;
            int t = j * CH_ + r;
            float lf = slp[r + 1];
            float lb = slp[CH_ - r];
            float cden = (i ? cs1 : cs0)
                       + lf * (i ? cqf1 : cqf0)
                       + lb * (i ? cqb1 : cqb0);
            float inv = 1.f / fmaxf(cden, 1e-6f);
            uint32_t hp[4], lp[4];
#pragma unroll
            for (int u = 0; u < 4; u++){
                float y0 = (aA[i][2*u]   + lf*aIf[i][2*u]   + lb*aIb[i][2*u]  ) * inv;
                float y1 = (aA[i][2*u+1] + lf*aIf[i][2*u+1] + lb*aIb[i][2*u+1]) * inv;
                float l0, l1;
                hp[u] = pack2h(y0, y1, &l0, &l1);
                lp[u] = pack2l(l0, l1);
            }
            size_t dst = ((size_t)(b * T_ + t) * D_) + h * HD_ + c0;
            *(uint4*)(g_ath + dst) = make_uint4(hp[0], hp[1], hp[2], hp[3]);
            *(uint4*)(g_atl + dst) = make_uint4(lp[0], lp[1], lp[2], lp[3]);
        }
    }
}

// ------------------------- launcher ----------------------------------------
extern "C" void kernel_launch(void* const* d_in, const int* in_sizes, int n_in,
                              void* d_out, int out_size)
{
    const float* x    = (const float*)d_in[0];
    const float* Wq   = (const float*)d_in[2];
    const float* Wk   = (const float*)d_in[3];
    const float* Wv   = (const float*)d_in[4];
    const float* Wo   = (const float*)d_in[5];
    const float* bo   = (const float*)d_in[6];
    const float* g1   = (const float*)d_in[7];
    const float* b1   = (const float*)d_in[8];
    const float* g2   = (const float*)d_in[9];
    const float* b2   = (const float*)d_in[10];
    const float* W1   = (const float*)d_in[11];
    const float* bf1  = (const float*)d_in[12];
    const float* W2   = (const float*)d_in[13];
    const float* bf2  = (const float*)d_in[14];
    const float* dlog = (const float*)d_in[15];
    float* out = (float*)d_out;

#define SYM(p, s) cudaGetSymbolAddress((void**)&p, s)
    __half *xnh,*xnl,*ath,*atl,*h2h,*h2l,*f1h,*f1l;
    __half *wqkvh,*woh,*w1h,*w2h;
    float *QKV,*x2;
    SYM(xnh,g_xnh); SYM(xnl,g_xnl); SYM(ath,g_ath); SYM(atl,g_atl);
    SYM(h2h,g_h2h); SYM(h2l,g_h2l); SYM(f1h,g_f1h); SYM(f1l,g_f1l);
    SYM(wqkvh,g_wqkvh); SYM(woh,g_woh); SYM(w1h,g_w1h); SYM(w2h,g_w2h);
    SYM(QKV,g_QKV); SYM(x2,g_x2);
#undef SYM

    cudaFuncSetAttribute(tc_gemm_w64<4,512>, cudaFuncAttributeMaxDynamicSharedMemorySize, GEMM_SMEM);
    cudaFuncSetAttribute(tc_gemm_w64<3,512>, cudaFuncAttributeMaxDynamicSharedMemorySize, GEMM_SMEM);
    cudaFuncSetAttribute(tc_gemm64<512>,     cudaFuncAttributeMaxDynamicSharedMemorySize, GEMM64_SMEM);
    cudaFuncSetAttribute(tc_gemm64<2048>,    cudaFuncAttributeMaxDynamicSharedMemorySize, GEMM64_SMEM);
    cudaFuncSetAttribute(chunk_comb_kernel,  cudaFuncAttributeMaxDynamicSharedMemorySize, CC_SMEM_BYTES);

    dim3 blk(256);
    dim3 blk128(128);
    dim3 gQKV((3*D_) / 128, M_ / 128);  // (12, 32) = 384 CTAs
    dim3 gD64(D_ / 128, M_ / 64);       // (4, 64)  = 256 CTAs
    dim3 gF(F_ / 128, M_ / 128);        // (16, 32) = 512 CTAs

    // 0) all weight splits (hi only, vectorized), one launch
    split_all_kernel<<<786432/256, blk>>>(Wq, Wk, Wv, Wo, W1, W2);
    // 1) LN1 (+fp16 split)
    ln_split_kernel<<<M_, blk>>>(x, g1, b1, xnh, xnl);
    // 2) fused Q/K/V projection (4-warp 64x64-warp-tile GEMM)
    tc_gemm_w64<4,512><<<gQKV, blk128, GEMM_SMEM>>>(xnh, xnl, wqkvh, 3*D_,
                                                    nullptr, QKV, nullptr, nullptr);
    // 3) dual-direction two-level scan + fused chunk/combine
    usum_dual_kernel<<<NBH_ * NCH_, blk>>>(dlog);
    sweep_kernel<<<2 * NBH_ * 16, blk>>>(dlog);
    chunk_comb_kernel<<<NBH_ * NCH_, blk, CC_SMEM_BYTES>>>(dlog);
    // 4) Wo + bias + residual -> fp32 x2
    tc_gemm64<512><<<gD64, blk, GEMM64_SMEM>>>(ath, atl, woh, D_, bo, x, x2);
    // 5) LN2 (+fp16 split)
    ln_split_kernel<<<M_, blk>>>(x2, g2, b2, h2h, h2l);
    // 6) FFN up + GELU -> split fp16 (4-warp GEMM)
    tc_gemm_w64<3,512><<<gF, blk128, GEMM_SMEM>>>(h2h, h2l, w1h, F_, bf1,
                                                  nullptr, f1h, f1l);
    // 7) FFN down + bias + residual -> final output
    tc_gemm64<2048><<<gD64, blk, GEMM64_SMEM>>>(f1h, f1l, w2h, D_, bf2, x2, out);
}

// round 15
// speedup vs baseline: 1.0364x; 1.0364x over previous
#include <cuda_runtime.h>
#include <cuda_fp16.h>
#include <math.h>
#include <stdint.h>

#define B_   2
#define T_   2048
#define D_   512
#define H_   8
#define HD_  64
#define F_   2048
#define M_   (B_*T_)
#define CH_  64
#define NCH_ (T_/CH_)
#define NBH_ (B_*H_)
#define QKVO (NBH_*T_*HD_)

// ------------------------- scratch globals ---------------------------------
__device__ __half g_xnh[M_*D_], g_xnl[M_*D_];
__device__ __half g_ath[M_*D_], g_atl[M_*D_];
__device__ __half g_h2h[M_*D_], g_h2l[M_*D_];
__device__ __half g_f1h[M_*F_], g_f1l[M_*F_];
__device__ __half g_wqkvh[3*D_*D_];          // Wq|Wk|Wv rows (hi only)
__device__ __half g_woh[D_*D_];
__device__ __half g_w1h[F_*D_];
__device__ __half g_w2h[D_*F_];
__device__ float g_QKV[3*QKVO];              // Q|K|V [b,h,t,e]
__device__ float g_x2[M_*D_];
__device__ float g_Schk[2*NBH_*NCH_*HD_*HD_];
__device__ float g_zchk[2*NBH_*NCH_*HD_];
__device__ float g_U   [2*NBH_*NCH_*HD_*HD_];
__device__ float g_zU  [2*NBH_*NCH_*HD_];

// ------------------------- helpers -----------------------------------------
static __device__ __forceinline__ uint32_t stou(const void* p){
    uint32_t a;
    asm("{ .reg .u64 t; cvta.to.shared.u64 t, %1; cvt.u32.u64 %0, t; }" : "=r"(a) : "l"(p));
    return a;
}
static __device__ __forceinline__ void cp16(uint32_t dst, const void* src){
    asm volatile("cp.async.cg.shared.global [%0], [%1], 16;" :: "r"(dst), "l"(src));
}
static __device__ __forceinline__ void ldm4(uint32_t* a, uint32_t addr){
    asm volatile("ldmatrix.sync.aligned.m8n8.x4.shared.b16 {%0,%1,%2,%3}, [%4];"
        : "=r"(a[0]),"=r"(a[1]),"=r"(a[2]),"=r"(a[3]) : "r"(addr));
}
static __device__ __forceinline__ void mma16816(float* c, const uint32_t* a, const uint32_t* b){
    asm volatile("mma.sync.aligned.m16n8k16.row.col.f32.f16.f16.f32 "
        "{%0,%1,%2,%3}, {%4,%5,%6,%7}, {%8,%9}, {%0,%1,%2,%3};"
        : "+f"(c[0]),"+f"(c[1]),"+f"(c[2]),"+f"(c[3])
        : "r"(a[0]),"r"(a[1]),"r"(a[2]),"r"(a[3]), "r"(b[0]),"r"(b[1]));
}
static __device__ __forceinline__ uint32_t pack2h(float a, float b, float* la, float* lb){
    __half ha = __float2half(a), hb = __float2half(b);
    *la = a - __half2float(ha);
    *lb = b - __half2float(hb);
    return (uint32_t)__half_as_ushort(ha) | ((uint32_t)__half_as_ushort(hb) << 16);
}
static __device__ __forceinline__ uint32_t pack2l(float la, float lb){
    return (uint32_t)__half_as_ushort(__float2half(la)) |
           ((uint32_t)__half_as_ushort(__float2half(lb)) << 16);
}

#define ROWB  144
#define ATILE 18432
#define STGB  36864
#define GEMM_SMEM (2*STGB)
#define BOFF64  9216
#define STGB64  27648
#define GEMM64_SMEM (2*STGB64)

// ---------------------------------------------------------------------------
// 128x128 split-fp16 GEMM (K'=2K), 2-stage, 8 warps, warp tile 64x32.
// B fragments loaded with x4 ldmatrix (2 n-tiles x 2 k-halves per issue).
// MODE: 3=bias+gelu->split fp16   4=fused QKV scatter (elu for n<1024)
// ---------------------------------------------------------------------------
template<int MODE, int KDIM>
__global__ void __launch_bounds__(256,2) tc_gemm(
    const __half* __restrict__ Ah, const __half* __restrict__ Al,
    const __half* __restrict__ Bh,
    int N, const float* __restrict__ bias,
    float* __restrict__ outF,
    __half* __restrict__ outH, __half* __restrict__ outL)
{
    extern __shared__ char dyns[];
    uint32_t sb = stou(dyns);

    int tid = threadIdx.x;
    int lane = tid & 31, w = tid >> 5;
    int warp_m = w >> 2, warp_n = w & 3;
    int m0 = blockIdx.y * 128;
    int n0 = blockIdx.x * 128;

    float acc[4][4][4];
#pragma unroll
    for (int i=0;i<4;i++)
#pragma unroll
        for (int j=0;j<4;j++)
#pragma unroll
            for (int k=0;k<4;k++) acc[i][j][k] = 0.f;

    const int NIT = 2*KDIM/64;

    auto fill = [&](int itf){
        int st = itf & 1;
        int kp = itf * 64;
        int pass = kp / KDIM;
        int koff = kp - pass*KDIM;
        const __half* pA = pass ? Al : Ah;
        uint32_t base = sb + st*STGB;
#pragma unroll
        for (int i=0;i<8;i++){
            int q = tid + i*256;
            int isB = q >> 10;
            int r   = (q >> 3) & 127;
            int c16 = q & 7;
            const __half* src =
                (isB ? (Bh + (size_t)(n0+r)*KDIM) : (pA + (size_t)(m0+r)*KDIM)) + koff + c16*8;
            cp16(base + isB*ATILE + r*ROWB + c16*16, src);
        }
        asm volatile("cp.async.commit_group;" ::: "memory");
    };

    uint32_t aBase = (uint32_t)((warp_m*64 + (lane & 15))*ROWB + ((lane >> 4) << 4));
    // B x4: lane b3 = k-half, lane b4 = nt-within-pair
    uint32_t bBase = (uint32_t)(ATILE +
        (warp_n*32 + ((lane >> 4) << 3) + (lane & 7))*ROWB + (((lane >> 3) & 1) << 4));

    fill(0);
    for (int it=0; it<NIT; ++it){
        if (it+1 < NIT){
            fill(it+1);
            asm volatile("cp.async.wait_group 1;" ::: "memory");
        } else {
            asm volatile("cp.async.wait_group 0;" ::: "memory");
        }
        __syncthreads();
        uint32_t stg = sb + (it&1)*STGB;
#pragma unroll
        for (int kk=0; kk<64; kk+=16){
            uint32_t afrag[4][4], bfrag[4][2];
#pragma unroll
            for (int mt=0;mt<4;mt++) ldm4(afrag[mt], stg + aBase + mt*(16*ROWB) + kk*2);
#pragma unroll
            for (int p=0;p<2;p++){
                uint32_t r4[4];
                ldm4(r4, stg + bBase + p*(16*ROWB) + kk*2);
                bfrag[2*p][0]=r4[0];   bfrag[2*p][1]=r4[1];
                bfrag[2*p+1][0]=r4[2]; bfrag[2*p+1][1]=r4[3];
            }
#pragma unroll
            for (int mt=0;mt<4;mt++)
#pragma unroll
                for (int nt=0;nt<4;nt++) mma16816(acc[mt][nt], afrag[mt], bfrag[nt]);
        }
        __syncthreads();
    }

    int mb = m0 + warp_m*64;
    int nb = n0 + warp_n*32;
#pragma unroll
    for (int mt=0; mt<4; mt++){
#pragma unroll
        for (int half=0; half<2; half++){
            int m = mb + mt*16 + (lane>>2) + half*8;
            int bb = m >> 11, tt = m & (T_-1);
#pragma unroll
            for (int nt=0; nt<4; nt++){
                int n = nb + nt*8 + (lane&3)*2;
                float v0 = acc[mt][nt][half*2];
                float v1 = acc[mt][nt][half*2+1];
                if (MODE == 4){
                    int mat = n >> 9;              // 0=Q 1=K 2=V
                    if (mat < 2){
                        v0 = v0>0.f ? v0+1.f : expf(v0);
                        v1 = v1>0.f ? v1+1.f : expf(v1);
                    }
                    int hh = (n >> 6) & 7, ee = n & 63;
                    float* dst = outF + (size_t)mat*QKVO
                               + ((((size_t)(bb*H_ + hh))*T_ + tt)<<6) + ee;
                    float2 o; o.x=v0; o.y=v1;
                    *(float2*)dst = o;
                } else {   // MODE 3: bias + exact GELU -> split fp16
                    size_t idx = (size_t)m*N + n;
                    float a = v0 + bias[n];
                    float b = v1 + bias[n+1];
                    a = 0.5f*a*(1.f+erff(a*0.70710678118654752f));
                    b = 0.5f*b*(1.f+erff(b*0.70710678118654752f));
                    float la, lb;
                    uint32_t hp = pack2h(a, b, &la, &lb);
                    uint32_t lp = pack2l(la, lb);
                    *(uint32_t*)(outH + idx) = hp;
                    *(uint32_t*)(outL + idx) = lp;
                }
            }
        }
    }
}

// ---------------------------------------------------------------------------
// 64x128 split-fp16 GEMM, 2-stage, 3 CTAs/SM. bias+res -> fp32.
// B fragments via x4 ldmatrix.
// ---------------------------------------------------------------------------
template<int KDIM>
__global__ void __launch_bounds__(256,3) tc_gemm64(
    const __half* __restrict__ Ah, const __half* __restrict__ Al,
    const __half* __restrict__ Bh,
    int N, const float* __restrict__ bias, const float* __restrict__ res,
    float* __restrict__ outF)
{
    extern __shared__ char dyns[];
    uint32_t sb = stou(dyns);

    int tid = threadIdx.x;
    int lane = tid & 31, w = tid >> 5;
    int warp_m = w >> 2, warp_n = w & 3;
    int m0 = blockIdx.y * 64;
    int n0 = blockIdx.x * 128;

    float acc[2][4][4];
#pragma unroll
    for (int i=0;i<2;i++)
#pragma unroll
        for (int j=0;j<4;j++)
#pragma unroll
            for (int k=0;k<4;k++) acc[i][j][k] = 0.f;

    const int NIT = 2*KDIM/64;

    auto fill = [&](int itf){
        int st = itf & 1;
        int kp = itf * 64;
        int pass = kp / KDIM;
        int koff = kp - pass*KDIM;
        const __half* pA = pass ? Al : Ah;
        uint32_t base = sb + st*STGB64;
#pragma unroll
        for (int i=0;i<6;i++){
            int q = tid + i*256;
            if (q < 512){
                int r = q >> 3, c16 = q & 7;
                cp16(base + r*ROWB + c16*16,
                     pA + (size_t)(m0+r)*KDIM + koff + c16*8);
            } else {
                int q2 = q - 512;
                int r = q2 >> 3, c16 = q2 & 7;
                cp16(base + BOFF64 + r*ROWB + c16*16,
                     Bh + (size_t)(n0+r)*KDIM + koff + c16*8);
            }
        }
        asm volatile("cp.async.commit_group;" ::: "memory");
    };

    uint32_t aBase = (uint32_t)((warp_m*32 + (lane & 15))*ROWB + ((lane >> 4) << 4));
    uint32_t bBase = (uint32_t)(BOFF64 +
        (warp_n*32 + ((lane >> 4) << 3) + (lane & 7))*ROWB + (((lane >> 3) & 1) << 4));

    fill(0);
    for (int it=0; it<NIT; ++it){
        if (it+1 < NIT){
            fill(it+1);
            asm volatile("cp.async.wait_group 1;" ::: "memory");
        } else {
            asm volatile("cp.async.wait_group 0;" ::: "memory");
        }
        __syncthreads();
        uint32_t stg = sb + (it&1)*STGB64;
#pragma unroll
        for (int kk=0; kk<64; kk+=16){
            uint32_t afrag[2][4], bfrag[4][2];
#pragma unroll
            for (int mt=0;mt<2;mt++) ldm4(afrag[mt], stg + aBase + mt*(16*ROWB) + kk*2);
#pragma unroll
            for (int p=0;p<2;p++){
                uint32_t r4[4];
                ldm4(r4, stg + bBase + p*(16*ROWB) + kk*2);
                bfrag[2*p][0]=r4[0];   bfrag[2*p][1]=r4[1];
                bfrag[2*p+1][0]=r4[2]; bfrag[2*p+1][1]=r4[3];
            }
#pragma unroll
            for (int mt=0;mt<2;mt++)
#pragma unroll
                for (int nt=0;nt<4;nt++) mma16816(acc[mt][nt], afrag[mt], bfrag[nt]);
        }
        __syncthreads();
    }

    int mb = m0 + warp_m*32;
    int nb = n0 + warp_n*32;
#pragma unroll
    for (int mt=0; mt<2; mt++){
#pragma unroll
        for (int half=0; half<2; half++){
            int m = mb + mt*16 + (lane>>2) + half*8;
#pragma unroll
            for (int nt=0; nt<4; nt++){
                int n = nb + nt*8 + (lane&3)*2;
                float v0 = acc[mt][nt][half*2];
                float v1 = acc[mt][nt][half*2+1];
                size_t idx = (size_t)m*N + n;
                float2 rv = *(const float2*)(res + idx);
                float2 o;
                o.x = v0 + bias[n]   + rv.x;
                o.y = v1 + bias[n+1] + rv.y;
                *(float2*)(outF + idx) = o;
            }
        }
    }
}

// ------------------------- batched weight split (hi only, vectorized) -------
__global__ void __launch_bounds__(256) split_all_kernel(
    const float* __restrict__ Wq, const float* __restrict__ Wk,
    const float* __restrict__ Wv, const float* __restrict__ Wo,
    const float* __restrict__ W1, const float* __restrict__ W2)
{
    int g = blockIdx.x * 256 + threadIdx.x;
    const float* src; __half* dh;
    if (g < 196608){
        int which = g >> 16;
        int j = g & 65535;
        src = (which==0 ? Wq : which==1 ? Wk : Wv) + j*4;
        dh = g_wqkvh + ((size_t)which << 18) + j*4;
    } else if (g < 262144){
        int j = g - 196608; src = Wo + (size_t)j*4; dh = g_woh + (size_t)j*4;
    } else if (g < 524288){
        int j = g - 262144; src = W1 + (size_t)j*4; dh = g_w1h + (size_t)j*4;
    } else {
        int j = g - 524288; src = W2 + (size_t)j*4; dh = g_w2h + (size_t)j*4;
    }
    float4 v = *(const float4*)src;
    uint2 hp;
    hp.x = (uint32_t)__half_as_ushort(__float2half(v.x)) |
           ((uint32_t)__half_as_ushort(__float2half(v.y)) << 16);
    hp.y = (uint32_t)__half_as_ushort(__float2half(v.z)) |
           ((uint32_t)__half_as_ushort(__float2half(v.w)) << 16);
    *(uint2*)dh = hp;
}

// ------------------------- LayerNorm + fp16 split ---------------------------
__global__ void __launch_bounds__(256) ln_split_kernel(
    const float* __restrict__ x, const float* __restrict__ g,
    const float* __restrict__ b, __half* __restrict__ yh,
    __half* __restrict__ yl)
{
    int row = blockIdx.x;
    const float* xr = x + (size_t)row * D_;
    int tid = threadIdx.x;
    float v0 = xr[tid], v1 = xr[tid + 256];
    float s  = v0 + v1, ss = v0*v0 + v1*v1;
    __shared__ float sh[16];
#pragma unroll
    for (int o = 16; o; o >>= 1) {
        s  += __shfl_xor_sync(0xffffffffu, s,  o);
        ss += __shfl_xor_sync(0xffffffffu, ss, o);
    }
    int w = tid >> 5;
    if ((tid & 31) == 0) { sh[w] = s; sh[w + 8] = ss; }
    __syncthreads();
    float S = 0.f, SS = 0.f;
#pragma unroll
    for (int i = 0; i < 8; i++) { S += sh[i]; SS += sh[8 + i]; }
    float mean = S * (1.0f / D_);
    float rstd = rsqrtf(SS * (1.0f / D_) - mean*mean + 1e-5f);
    size_t base = (size_t)row * D_;
    float o0 = (v0 - mean) * rstd * g[tid]       + b[tid];
    float o1 = (v1 - mean) * rstd * g[tid + 256] + b[tid + 256];
    __half h0 = __float2half(o0), h1 = __float2half(o1);
    yh[base + tid]       = h0;
    yh[base + tid + 256] = h1;
    yl[base + tid]       = __float2half(o0 - __half2float(h0));
    yl[base + tid + 256] = __float2half(o1 - __half2float(h1));
}

// ---------------------------------------------------------------------------
// Scan level 1 (DUAL direction) — validated R12, unchanged
// ---------------------------------------------------------------------------
__global__ void __launch_bounds__(256) usum_dual_kernel(const float* __restrict__ dlogit)
{
    int bx  = blockIdx.x;
    int j   = bx & 31;
    int bh  = bx >> 5;
    int h   = bh & 7;
    float lam = 1.f / (1.f + expf(-dlogit[h]));

    __shared__ float sK[CH_ * HD_];
    __shared__ float sV[CH_ * HD_];
    __shared__ float wf[CH_], wb[CH_];

    int tid = threadIdx.x;
    if (tid < CH_){
        wf[tid] = powf(lam, (float)(CH_ - 1 - tid));
        wb[tid] = powf(lam, (float)tid);
    }

    int lrow = tid >> 2;
    int lseg = (tid & 3) * 16;
    int pt = j * CH_ + lrow;
    const float* Kg = g_QKV + QKVO     + (size_t)bh * T_ * HD_;
    const float* Vg = g_QKV + 2*QKVO   + (size_t)bh * T_ * HD_;
    {
        const float4* kr = (const float4*)(Kg + (size_t)pt * HD_ + lseg);
        const float4* vr = (const float4*)(Vg + (size_t)pt * HD_ + lseg);
        float4* sk = (float4*)(sK + lrow * HD_ + lseg);
        float4* sv = (float4*)(sV + lrow * HD_ + lseg);
        sk[0]=kr[0]; sk[1]=kr[1]; sk[2]=kr[2]; sk[3]=kr[3];
        sv[0]=vr[0]; sv[1]=vr[1]; sv[2]=vr[2]; sv[3]=vr[3];
    }
    __syncthreads();

    int d = tid & 63, c = tid >> 6;
    int e0 = c * 16;
    float aF[16], aB[16];
#pragma unroll
    for (int i = 0; i < 16; i++){ aF[i] = 0.f; aB[i] = 0.f; }
    float zF = 0.f, zB = 0.f;

#pragma unroll 4
    for (int s = 0; s < CH_; s++){
        float kr = sK[s * HD_ + d];
        float kf = kr * wf[s];
        float kb = kr * wb[s];
        zF += kf; zB += kb;
        const float4* vv = (const float4*)(sV + s * HD_ + e0);
        float4 a0 = vv[0], a1 = vv[1], a2 = vv[2], a3 = vv[3];
        aF[0]=fmaf(kf,a0.x,aF[0]); aB[0]=fmaf(kb,a0.x,aB[0]);
        aF[1]=fmaf(kf,a0.y,aF[1]); aB[1]=fmaf(kb,a0.y,aB[1]);
        aF[2]=fmaf(kf,a0.z,aF[2]); aB[2]=fmaf(kb,a0.z,aB[2]);
        aF[3]=fmaf(kf,a0.w,aF[3]); aB[3]=fmaf(kb,a0.w,aB[3]);
        aF[4]=fmaf(kf,a1.x,aF[4]); aB[4]=fmaf(kb,a1.x,aB[4]);
        aF[5]=fmaf(kf,a1.y,aF[5]); aB[5]=fmaf(kb,a1.y,aB[5]);
        aF[6]=fmaf(kf,a1.z,aF[6]); aB[6]=fmaf(kb,a1.z,aB[6]);
        aF[7]=fmaf(kf,a1.w,aF[7]); aB[7]=fmaf(kb,a1.w,aB[7]);
        aF[8]=fmaf(kf,a2.x,aF[8]); aB[8]=fmaf(kb,a2.x,aB[8]);
        aF[9]=fmaf(kf,a2.y,aF[9]); aB[9]=fmaf(kb,a2.y,aB[9]);
        aF[10]=fmaf(kf,a2.z,aF[10]); aB[10]=fmaf(kb,a2.z,aB[10]);
        aF[11]=fmaf(kf,a2.w,aF[11]); aB[11]=fmaf(kb,a2.w,aB[11]);
        aF[12]=fmaf(kf,a3.x,aF[12]); aB[12]=fmaf(kb,a3.x,aB[12]);
        aF[13]=fmaf(kf,a3.y,aF[13]); aB[13]=fmaf(kb,a3.y,aB[13]);
        aF[14]=fmaf(kf,a3.z,aF[14]); aB[14]=fmaf(kb,a3.z,aB[14]);
        aF[15]=fmaf(kf,a3.w,aF[15]); aB[15]=fmaf(kb,a3.w,aB[15]);
    }

    float* Uf = g_U + (size_t)((0 * NBH_ + bh) * NCH_ + j) * (HD_ * HD_);
    float* Ub = g_U + (size_t)((1 * NBH_ + bh) * NCH_ + (NCH_ - 1 - j)) * (HD_ * HD_);
#pragma unroll
    for (int i = 0; i < 16; i++){
        Uf[(e0 + i) * 64 + d] = aF[i];
        Ub[(e0 + i) * 64 + d] = aB[i];
    }
    if (c == 0){
        g_zU[(size_t)((0 * NBH_ + bh) * NCH_ + j) * HD_ + d] = zF;
        g_zU[(size_t)((1 * NBH_ + bh) * NCH_ + (NCH_ - 1 - j)) * HD_ + d] = zB;
    }
}

// ---------------------------------------------------------------------------
// Scan level 2: sweep — validated, unchanged
// ---------------------------------------------------------------------------
__global__ void __launch_bounds__(256) sweep_kernel(const float* __restrict__ dlogit)
{
    int bx  = blockIdx.x;
    int seg = bx & 15;
    int bh  = (bx >> 4) & 15;
    int dir = bx >> 8;
    int h   = bh & 7;
    float lam  = 1.f / (1.f + expf(-dlogit[h]));
    float lamC = powf(lam, (float)CH_);

    int el = seg * 256 + threadIdx.x;
    size_t base = (size_t)((dir * NBH_ + bh) * NCH_) * (HD_ * HD_);
    float S = 0.f;
#pragma unroll
    for (int jj = 0; jj < NCH_; jj++){
        size_t o = base + (size_t)jj * (HD_ * HD_) + el;
        float u = g_U[o];
        g_Schk[o] = S;
        S = fmaf(lamC, S, u);
    }
    if (seg == 0 && threadIdx.x < HD_){
        int d = threadIdx.x;
        size_t zb = (size_t)((dir * NBH_ + bh) * NCH_) * HD_;
        float z = 0.f;
#pragma unroll
        for (int jj = 0; jj < NCH_; jj++){
            float zu = g_zU[zb + jj * HD_ + d];
            g_zchk[zb + jj * HD_ + d] = z;
            z = fmaf(lamC, z, zu);
        }
    }
}

// ---------------------------------------------------------------------------
// Combined dual-direction chunk kernel — validated R12/R13, unchanged
// ---------------------------------------------------------------------------
#define COFF_Q   0
#define COFF_K   4160
#define COFF_P   8320
#define COFF_V   12480
#define COFF_SF  16576
#define COFF_SB  20928
#define COFF_ZF  25280
#define COFF_ZB  25344
#define COFF_LP  25408
#define CC_SMEM_BYTES ((25408 + 80) * 4)

__global__ void __launch_bounds__(256) chunk_comb_kernel(const float* __restrict__ dlogit)
{
    extern __shared__ float sm[];
    float* sQ  = sm + COFF_Q;
    float* sK  = sm + COFF_K;
    float* sP  = sm + COFF_P;
    float* sV  = sm + COFF_V;
    float* sSf = sm + COFF_SF;
    float* sSb = sm + COFF_SB;
    float* szf = sm + COFF_ZF;
    float* szb = sm + COFF_ZB;
    float* slp = sm + COFF_LP;

    int bx  = blockIdx.x;
    int j   = bx & 31;
    int bh  = bx >> 5;
    int h   = bh & 7;
    float lam = 1.f / (1.f + expf(-dlogit[h]));

    int tid = threadIdx.x;
    if (tid <= CH_) slp[tid] = powf(lam, (float)tid);

    const float* Qg  = g_QKV            + (size_t)bh * T_ * HD_;
    const float* Kg  = g_QKV + QKVO     + (size_t)bh * T_ * HD_;
    const float* Vg  = g_QKV + 2*QKVO   + (size_t)bh * T_ * HD_;
    const float* Sfin = g_Schk + (size_t)((0 * NBH_ + bh) * NCH_ + j) * (HD_ * HD_);
    const float* Sbin = g_Schk + (size_t)((1 * NBH_ + bh) * NCH_ + (NCH_ - 1 - j)) * (HD_ * HD_);
    const float* zfin = g_zchk + (size_t)((0 * NBH_ + bh) * NCH_ + j) * HD_;
    const float* zbin = g_zchk + (size_t)((1 * NBH_ + bh) * NCH_ + (NCH_ - 1 - j)) * HD_;

    int lrow = tid >> 2;
    int lseg = (tid & 3) * 16;
    int pt0 = j * CH_ + lrow;

#pragma unroll 4
    for (int i = 0; i < 16; i++) {
        sQ[lrow * 65 + lseg + i] = Qg[(size_t)pt0 * HD_ + lseg + i];
        sK[lrow * 65 + lseg + i] = Kg[(size_t)pt0 * HD_ + lseg + i];
    }
    {
        float4* svr = (float4*)(sV + lrow * 64 + lseg);
        const float4* vr = (const float4*)(Vg + (size_t)pt0 * HD_ + lseg);
        svr[0]=vr[0]; svr[1]=vr[1]; svr[2]=vr[2]; svr[3]=vr[3];
    }
#pragma unroll 4
    for (int i = 0; i < 16; i++) {
        int idx = tid * 16 + i;
        int e = idx >> 6, dd = idx & 63;
        sSf[dd * 68 + e] = Sfin[idx];
        sSb[dd * 68 + e] = Sbin[idx];
    }
    if (tid < 64){ szf[tid] = zfin[tid]; szb[tid] = zbin[tid]; }
    __syncthreads();

    {
        int ty = tid >> 4, tx = tid & 15;
        int r0 = ty * 4, c0 = tx * 4;
        float acc[4][4];
#pragma unroll
        for (int i = 0; i < 4; i++)
#pragma unroll
            for (int jc = 0; jc < 4; jc++) acc[i][jc] = 0.f;

        for (int d = 0; d < 64; d++) {
            float q0 = sQ[(r0+0)*65+d], q1 = sQ[(r0+1)*65+d];
            float q2 = sQ[(r0+2)*65+d], q3 = sQ[(r0+3)*65+d];
            float k0 = sK[(c0+0)*65+d], k1 = sK[(c0+1)*65+d];
            float k2 = sK[(c0+2)*65+d], k3 = sK[(c0+3)*65+d];
            acc[0][0]=fmaf(q0,k0,acc[0][0]); acc[0][1]=fmaf(q0,k1,acc[0][1]);
            acc[0][2]=fmaf(q0,k2,acc[0][2]); acc[0][3]=fmaf(q0,k3,acc[0][3]);
            acc[1][0]=fmaf(q1,k0,acc[1][0]); acc[1][1]=fmaf(q1,k1,acc[1][1]);
            acc[1][2]=fmaf(q1,k2,acc[1][2]); acc[1][3]=fmaf(q1,k3,acc[1][3]);
            acc[2][0]=fmaf(q2,k0,acc[2][0]); acc[2][1]=fmaf(q2,k1,acc[2][1]);
            acc[2][2]=fmaf(q2,k2,acc[2][2]); acc[2][3]=fmaf(q2,k3,acc[2][3]);
            acc[3][0]=fmaf(q3,k0,acc[3][0]); acc[3][1]=fmaf(q3,k1,acc[3][1]);
            acc[3][2]=fmaf(q3,k2,acc[3][2]); acc[3][3]=fmaf(q3,k3,acc[3][3]);
        }
#pragma unroll
        for (int i = 0; i < 4; i++) {
            int r = r0 + i;
#pragma unroll
            for (int jc = 0; jc < 4; jc++) {
                int cc = c0 + jc;
                int dlt = r >= cc ? r - cc : cc - r;
                sP[r * 65 + cc] = acc[i][jc] * slp[dlt];
            }
        }
    }
    __syncthreads();

    {
        int rr = (tid >> 3) * 2;
        int c0 = (tid & 7) * 8;
        float aA[2][8], aIf[2][8], aIb[2][8];
#pragma unroll
        for (int i = 0; i < 2; i++)
#pragma unroll
            for (int jc = 0; jc < 8; jc++){ aA[i][jc]=0.f; aIf[i][jc]=0.f; aIb[i][jc]=0.f; }
        float cs0 = 0.f, cs1 = 0.f;
        float cqf0 = 0.f, cqf1 = 0.f, cqb0 = 0.f, cqb1 = 0.f;

        for (int s = 0; s < 64; s++) {
            float a0 = sP[rr * 65 + s];
            float a1 = sP[(rr + 1) * 65 + s];
            cs0 += a0; cs1 += a1;
            float4 v0 = *(const float4*)(sV + s * 64 + c0);
            float4 v1 = *(const float4*)(sV + s * 64 + c0 + 4);
            aA[0][0]=fmaf(a0,v0.x,aA[0][0]); aA[0][1]=fmaf(a0,v0.y,aA[0][1]);
            aA[0][2]=fmaf(a0,v0.z,aA[0][2]); aA[0][3]=fmaf(a0,v0.w,aA[0][3]);
            aA[0][4]=fmaf(a0,v1.x,aA[0][4]); aA[0][5]=fmaf(a0,v1.y,aA[0][5]);
            aA[0][6]=fmaf(a0,v1.z,aA[0][6]); aA[0][7]=fmaf(a0,v1.w,aA[0][7]);
            aA[1][0]=fmaf(a1,v0.x,aA[1][0]); aA[1][1]=fmaf(a1,v0.y,aA[1][1]);
            aA[1][2]=fmaf(a1,v0.z,aA[1][2]); aA[1][3]=fmaf(a1,v0.w,aA[1][3]);
            aA[1][4]=fmaf(a1,v1.x,aA[1][4]); aA[1][5]=fmaf(a1,v1.y,aA[1][5]);
            aA[1][6]=fmaf(a1,v1.z,aA[1][6]); aA[1][7]=fmaf(a1,v1.w,aA[1][7]);
        }
        for (int d = 0; d < 64; d++) {
            float q0 = sQ[rr * 65 + d];
            float q1 = sQ[(rr + 1) * 65 + d];
            cqf0 = fmaf(q0, szf[d], cqf0);
            cqf1 = fmaf(q1, szf[d], cqf1);
            cqb0 = fmaf(q0, szb[d], cqb0);
            cqb1 = fmaf(q1, szb[d], cqb1);
            float4 f0 = *(const float4*)(sSf + d * 68 + c0);
            float4 f1 = *(const float4*)(sSf + d * 68 + c0 + 4);
            float4 b0 = *(const float4*)(sSb + d * 68 + c0);
            float4 b1 = *(const float4*)(sSb + d * 68 + c0 + 4);
            aIf[0][0]=fmaf(q0,f0.x,aIf[0][0]); aIf[0][1]=fmaf(q0,f0.y,aIf[0][1]);
            aIf[0][2]=fmaf(q0,f0.z,aIf[0][2]); aIf[0][3]=fmaf(q0,f0.w,aIf[0][3]);
            aIf[0][4]=fmaf(q0,f1.x,aIf[0][4]); aIf[0][5]=fmaf(q0,f1.y,aIf[0][5]);
            aIf[0][6]=fmaf(q0,f1.z,aIf[0][6]); aIf[0][7]=fmaf(q0,f1.w,aIf[0][7]);
            aIf[1][0]=fmaf(q1,f0.x,aIf[1][0]); aIf[1][1]=fmaf(q1,f0.y,aIf[1][1]);
            aIf[1][2]=fmaf(q1,f0.z,aIf[1][2]); aIf[1][3]=fmaf(q1,f0.w,aIf[1][3]);
            aIf[1][4]=fmaf(q1,f1.x,aIf[1][4]); aIf[1][5]=fmaf(q1,f1.y,aIf[1][5]);
            aIf[1][6]=fmaf(q1,f1.z,aIf[1][6]); aIf[1][7]=fmaf(q1,f1.w,aIf[1][7]);
            aIb[0][0]=fmaf(q0,b0.x,aIb[0][0]); aIb[0][1]=fmaf(q0,b0.y,aIb[0][1]);
            aIb[0][2]=fmaf(q0,b0.z,aIb[0][2]); aIb[0][3]=fmaf(q0,b0.w,aIb[0][3]);
            aIb[0][4]=fmaf(q0,b1.x,aIb[0][4]); aIb[0][5]=fmaf(q0,b1.y,aIb[0][5]);
            aIb[0][6]=fmaf(q0,b1.z,aIb[0][6]); aIb[0][7]=fmaf(q0,b1.w,aIb[0][7]);
            aIb[1][0]=fmaf(q1,b0.x,aIb[1][0]); aIb[1][1]=fmaf(q1,b0.y,aIb[1][1]);
            aIb[1][2]=fmaf(q1,b0.z,aIb[1][2]); aIb[1][3]=fmaf(q1,b0.w,aIb[1][3]);
            aIb[1][4]=fmaf(q1,b1.x,aIb[1][4]); aIb[1][5]=fmaf(q1,b1.y,aIb[1][5]);
            aIb[1][6]=fmaf(q1,b1.z,aIb[1][6]); aIb[1][7]=fmaf(q1,b1.w,aIb[1][7]);
        }

        int b = bh >> 3;
#pragma unroll
        for (int i = 0; i < 2; i++) {
            int r = rr + i;
            int t = j * CH_ + r;
            float lf = slp[r + 1];
            float lb = slp[CH_ - r];
            float cden = (i ? cs1 : cs0)
                       + lf * (i ? cqf1 : cqf0)
                       + lb * (i ? cqb1 : cqb0);
            float inv = 1.f / fmaxf(cden, 1e-6f);
            uint32_t hp[4], lp[4];
#pragma unroll
            for (int u = 0; u < 4; u++){
                float y0 = (aA[i][2*u]   + lf*aIf[i][2*u]   + lb*aIb[i][2*u]  ) * inv;
                float y1 = (aA[i][2*u+1] + lf*aIf[i][2*u+1] + lb*aIb[i][2*u+1]) * inv;
                float l0, l1;
                hp[u] = pack2h(y0, y1, &l0, &l1);
                lp[u] = pack2l(l0, l1);
            }
            size_t dst = ((size_t)(b * T_ + t) * D_) + h * HD_ + c0;
            *(uint4*)(g_ath + dst) = make_uint4(hp[0], hp[1], hp[2], hp[3]);
            *(uint4*)(g_atl + dst) = make_uint4(lp[0], lp[1], lp[2], lp[3]);
        }
    }
}

// ------------------------- launcher ----------------------------------------
extern "C" void kernel_launch(void* const* d_in, const int* in_sizes, int n_in,
                              void* d_out, int out_size)
{
    const float* x    = (const float*)d_in[0];
    const float* Wq   = (const float*)d_in[2];
    const float* Wk   = (const float*)d_in[3];
    const float* Wv   = (const float*)d_in[4];
    const float* Wo   = (const float*)d_in[5];
    const float* bo   = (const float*)d_in[6];
    const float* g1   = (const float*)d_in[7];
    const float* b1   = (const float*)d_in[8];
    const float* g2   = (const float*)d_in[9];
    const float* b2   = (const float*)d_in[10];
    const float* W1   = (const float*)d_in[11];
    const float* bf1  = (const float*)d_in[12];
    const float* W2   = (const float*)d_in[13];
    const float* bf2  = (const float*)d_in[14];
    const float* dlog = (const float*)d_in[15];
    float* out = (float*)d_out;

#define SYM(p, s) cudaGetSymbolAddress((void**)&p, s)
    __half *xnh,*xnl,*ath,*atl,*h2h,*h2l,*f1h,*f1l;
    __half *wqkvh,*woh,*w1h,*w2h;
    float *QKV,*x2;
    SYM(xnh,g_xnh); SYM(xnl,g_xnl); SYM(ath,g_ath); SYM(atl,g_atl);
    SYM(h2h,g_h2h); SYM(h2l,g_h2l); SYM(f1h,g_f1h); SYM(f1l,g_f1l);
    SYM(wqkvh,g_wqkvh); SYM(woh,g_woh); SYM(w1h,g_w1h); SYM(w2h,g_w2h);
    SYM(QKV,g_QKV); SYM(x2,g_x2);
#undef SYM

    cudaFuncSetAttribute(tc_gemm<4,512>,   cudaFuncAttributeMaxDynamicSharedMemorySize, GEMM_SMEM);
    cudaFuncSetAttribute(tc_gemm<3,512>,   cudaFuncAttributeMaxDynamicSharedMemorySize, GEMM_SMEM);
    cudaFuncSetAttribute(tc_gemm64<512>,   cudaFuncAttributeMaxDynamicSharedMemorySize, GEMM64_SMEM);
    cudaFuncSetAttribute(tc_gemm64<2048>,  cudaFuncAttributeMaxDynamicSharedMemorySize, GEMM64_SMEM);
    cudaFuncSetAttribute(chunk_comb_kernel,cudaFuncAttributeMaxDynamicSharedMemorySize, CC_SMEM_BYTES);

    dim3 blk(256);
    dim3 gQKV((3*D_) / 128, M_ / 128);  // (12, 32) = 384 CTAs
    dim3 gD64(D_ / 128, M_ / 64);       // (4, 64)  = 256 CTAs
    dim3 gF(F_ / 128, M_ / 128);        // (16, 32) = 512 CTAs

    // 0) all weight splits (hi only, vectorized), one launch
    split_all_kernel<<<786432/256, blk>>>(Wq, Wk, Wv, Wo, W1, W2);
    // 1) LN1 (+fp16 split)
    ln_split_kernel<<<M_, blk>>>(x, g1, b1, xnh, xnl);
    // 2) fused Q/K/V projection (2-pass fp16 emulation)
    tc_gemm<4,512><<<gQKV, blk, GEMM_SMEM>>>(xnh, xnl, wqkvh, 3*D_,
                                             nullptr, QKV, nullptr, nullptr);
    // 3) dual-direction two-level scan + fused chunk/combine
    usum_dual_kernel<<<NBH_ * NCH_, blk>>>(dlog);
    sweep_kernel<<<2 * NBH_ * 16, blk>>>(dlog);
    chunk_comb_kernel<<<NBH_ * NCH_, blk, CC_SMEM_BYTES>>>(dlog);
    // 4) Wo + bias + residual -> fp32 x2
    tc_gemm64<512><<<gD64, blk, GEMM64_SMEM>>>(ath, atl, woh, D_, bo, x, x2);
    // 5) LN2 (+fp16 split)
    ln_split_kernel<<<M_, blk>>>(x2, g2, b2, h2h, h2l);
    // 6) FFN up + GELU -> split fp16
    tc_gemm<3,512><<<gF, blk, GEMM_SMEM>>>(h2h, h2l, w1h, F_, bf1, nullptr, f1h, f1l);
    // 7) FFN down + bias + residual -> final output
    tc_gemm64<2048><<<gD64, blk, GEMM64_SMEM>>>(f1h, f1l, w2h, D_, bf2, x2, out);
}

// round 16
// speedup vs baseline: 1.4228x; 1.3729x over previous
#include <cuda_runtime.h>
#include <cuda_fp16.h>
#include <math.h>
#include <stdint.h>

#define B_   2
#define T_   2048
#define D_   512
#define H_   8
#define HD_  64
#define F_   2048
#define M_   (B_*T_)
#define CH_  64
#define NCH_ (T_/CH_)
#define NBH_ (B_*H_)
#define QKVO (NBH_*T_*HD_)

// ------------------------- scratch globals ---------------------------------
__device__ __half g_xnh[M_*D_];
__device__ __half g_ath[M_*D_];
__device__ __half g_h2h[M_*D_];
__device__ __half g_f1h[M_*F_];
__device__ __half g_wqkvh[3*D_*D_];          // Wq|Wk|Wv rows
__device__ __half g_woh[D_*D_];
__device__ __half g_w1h[F_*D_];
__device__ __half g_w2h[D_*F_];
__device__ float g_QKV[3*QKVO];              // Q|K|V [b,h,t,e]
__device__ float g_x2[M_*D_];
__device__ float g_Schk[2*NBH_*NCH_*HD_*HD_];
__device__ float g_zchk[2*NBH_*NCH_*HD_];
__device__ float g_U   [2*NBH_*NCH_*HD_*HD_];
__device__ float g_zU  [2*NBH_*NCH_*HD_];

// ------------------------- helpers -----------------------------------------
static __device__ __forceinline__ uint32_t stou(const void* p){
    uint32_t a;
    asm("{ .reg .u64 t; cvta.to.shared.u64 t, %1; cvt.u32.u64 %0, t; }" : "=r"(a) : "l"(p));
    return a;
}
static __device__ __forceinline__ void cp16(uint32_t dst, const void* src){
    asm volatile("cp.async.cg.shared.global [%0], [%1], 16;" :: "r"(dst), "l"(src));
}
static __device__ __forceinline__ void ldm4(uint32_t* a, uint32_t addr){
    asm volatile("ldmatrix.sync.aligned.m8n8.x4.shared.b16 {%0,%1,%2,%3}, [%4];"
        : "=r"(a[0]),"=r"(a[1]),"=r"(a[2]),"=r"(a[3]) : "r"(addr));
}
static __device__ __forceinline__ void mma16816(float* c, const uint32_t* a, const uint32_t* b){
    asm volatile("mma.sync.aligned.m16n8k16.row.col.f32.f16.f16.f32 "
        "{%0,%1,%2,%3}, {%4,%5,%6,%7}, {%8,%9}, {%0,%1,%2,%3};"
        : "+f"(c[0]),"+f"(c[1]),"+f"(c[2]),"+f"(c[3])
        : "r"(a[0]),"r"(a[1]),"r"(a[2]),"r"(a[3]), "r"(b[0]),"r"(b[1]));
}
static __device__ __forceinline__ uint32_t pack2(float a, float b){
    return (uint32_t)__half_as_ushort(__float2half(a)) |
           ((uint32_t)__half_as_ushort(__float2half(b)) << 16);
}

#define ROWB  144
#define ATILE 18432
#define STGB  36864
#define GEMM_SMEM (2*STGB)
#define BOFF64  9216
#define STGB64  27648
#define GEMM64_SMEM (2*STGB64)

// ---------------------------------------------------------------------------
// 128x128 fp16 GEMM (single pass), 2-stage, 8 warps, warp tile 64x32.
// MODE: 3=bias+gelu->fp16   4=fused QKV scatter (elu for n<1024)
// ---------------------------------------------------------------------------
template<int MODE, int KDIM>
__global__ void __launch_bounds__(256,2) tc_gemm(
    const __half* __restrict__ Ah, const __half* __restrict__ Bh,
    int N, const float* __restrict__ bias,
    float* __restrict__ outF, __half* __restrict__ outH)
{
    extern __shared__ char dyns[];
    uint32_t sb = stou(dyns);

    int tid = threadIdx.x;
    int lane = tid & 31, w = tid >> 5;
    int warp_m = w >> 2, warp_n = w & 3;
    int m0 = blockIdx.y * 128;
    int n0 = blockIdx.x * 128;

    float acc[4][4][4];
#pragma unroll
    for (int i=0;i<4;i++)
#pragma unroll
        for (int j=0;j<4;j++)
#pragma unroll
            for (int k=0;k<4;k++) acc[i][j][k] = 0.f;

    const int NIT = KDIM/64;

    auto fill = [&](int itf){
        int st = itf & 1;
        int koff = itf * 64;
        uint32_t base = sb + st*STGB;
#pragma unroll
        for (int i=0;i<8;i++){
            int q = tid + i*256;
            int isB = q >> 10;
            int r   = (q >> 3) & 127;
            int c16 = q & 7;
            const __half* src =
                (isB ? (Bh + (size_t)(n0+r)*KDIM) : (Ah + (size_t)(m0+r)*KDIM)) + koff + c16*8;
            cp16(base + isB*ATILE + r*ROWB + c16*16, src);
        }
        asm volatile("cp.async.commit_group;" ::: "memory");
    };

    uint32_t aBase = (uint32_t)((warp_m*64 + (lane & 15))*ROWB + ((lane >> 4) << 4));
    uint32_t bBase = (uint32_t)(ATILE +
        (warp_n*32 + ((lane >> 4) << 3) + (lane & 7))*ROWB + (((lane >> 3) & 1) << 4));

    fill(0);
    for (int it=0; it<NIT; ++it){
        if (it+1 < NIT){
            fill(it+1);
            asm volatile("cp.async.wait_group 1;" ::: "memory");
        } else {
            asm volatile("cp.async.wait_group 0;" ::: "memory");
        }
        __syncthreads();
        uint32_t stg = sb + (it&1)*STGB;
#pragma unroll
        for (int kk=0; kk<64; kk+=16){
            uint32_t afrag[4][4], bfrag[4][2];
#pragma unroll
            for (int mt=0;mt<4;mt++) ldm4(afrag[mt], stg + aBase + mt*(16*ROWB) + kk*2);
#pragma unroll
            for (int p=0;p<2;p++){
                uint32_t r4[4];
                ldm4(r4, stg + bBase + p*(16*ROWB) + kk*2);
                bfrag[2*p][0]=r4[0];   bfrag[2*p][1]=r4[1];
                bfrag[2*p+1][0]=r4[2]; bfrag[2*p+1][1]=r4[3];
            }
#pragma unroll
            for (int mt=0;mt<4;mt++)
#pragma unroll
                for (int nt=0;nt<4;nt++) mma16816(acc[mt][nt], afrag[mt], bfrag[nt]);
        }
        __syncthreads();
    }

    int mb = m0 + warp_m*64;
    int nb = n0 + warp_n*32;
#pragma unroll
    for (int mt=0; mt<4; mt++){
#pragma unroll
        for (int half=0; half<2; half++){
            int m = mb + mt*16 + (lane>>2) + half*8;
            int bb = m >> 11, tt = m & (T_-1);
#pragma unroll
            for (int nt=0; nt<4; nt++){
                int n = nb + nt*8 + (lane&3)*2;
                float v0 = acc[mt][nt][half*2];
                float v1 = acc[mt][nt][half*2+1];
                if (MODE == 4){
                    int mat = n >> 9;              // 0=Q 1=K 2=V
                    if (mat < 2){
                        v0 = v0>0.f ? v0+1.f : expf(v0);
                        v1 = v1>0.f ? v1+1.f : expf(v1);
                    }
                    int hh = (n >> 6) & 7, ee = n & 63;
                    float* dst = outF + (size_t)mat*QKVO
                               + ((((size_t)(bb*H_ + hh))*T_ + tt)<<6) + ee;
                    float2 o; o.x=v0; o.y=v1;
                    *(float2*)dst = o;
                } else {   // MODE 3: bias + exact GELU -> fp16
                    size_t idx = (size_t)m*N + n;
                    float a = v0 + bias[n];
                    float b = v1 + bias[n+1];
                    a = 0.5f*a*(1.f+erff(a*0.70710678118654752f));
                    b = 0.5f*b*(1.f+erff(b*0.70710678118654752f));
                    *(uint32_t*)(outH + idx) = pack2(a, b);
                }
            }
        }
    }
}

// ---------------------------------------------------------------------------
// 64x128 fp16 GEMM (single pass), 2-stage, 3 CTAs/SM. bias+res -> fp32.
// ---------------------------------------------------------------------------
template<int KDIM>
__global__ void __launch_bounds__(256,3) tc_gemm64(
    const __half* __restrict__ Ah, const __half* __restrict__ Bh,
    int N, const float* __restrict__ bias, const float* __restrict__ res,
    float* __restrict__ outF)
{
    extern __shared__ char dyns[];
    uint32_t sb = stou(dyns);

    int tid = threadIdx.x;
    int lane = tid & 31, w = tid >> 5;
    int warp_m = w >> 2, warp_n = w & 3;
    int m0 = blockIdx.y * 64;
    int n0 = blockIdx.x * 128;

    float acc[2][4][4];
#pragma unroll
    for (int i=0;i<2;i++)
#pragma unroll
        for (int j=0;j<4;j++)
#pragma unroll
            for (int k=0;k<4;k++) acc[i][j][k] = 0.f;

    const int NIT = KDIM/64;

    auto fill = [&](int itf){
        int st = itf & 1;
        int koff = itf * 64;
        uint32_t base = sb + st*STGB64;
#pragma unroll
        for (int i=0;i<6;i++){
            int q = tid + i*256;
            if (q < 512){
                int r = q >> 3, c16 = q & 7;
                cp16(base + r*ROWB + c16*16,
                     Ah + (size_t)(m0+r)*KDIM + koff + c16*8);
            } else {
                int q2 = q - 512;
                int r = q2 >> 3, c16 = q2 & 7;
                cp16(base + BOFF64 + r*ROWB + c16*16,
                     Bh + (size_t)(n0+r)*KDIM + koff + c16*8);
            }
        }
        asm volatile("cp.async.commit_group;" ::: "memory");
    };

    uint32_t aBase = (uint32_t)((warp_m*32 + (lane & 15))*ROWB + ((lane >> 4) << 4));
    uint32_t bBase = (uint32_t)(BOFF64 +
        (warp_n*32 + ((lane >> 4) << 3) + (lane & 7))*ROWB + (((lane >> 3) & 1) << 4));

    fill(0);
    for (int it=0; it<NIT; ++it){
        if (it+1 < NIT){
            fill(it+1);
            asm volatile("cp.async.wait_group 1;" ::: "memory");
        } else {
            asm volatile("cp.async.wait_group 0;" ::: "memory");
        }
        __syncthreads();
        uint32_t stg = sb + (it&1)*STGB64;
#pragma unroll
        for (int kk=0; kk<64; kk+=16){
            uint32_t afrag[2][4], bfrag[4][2];
#pragma unroll
            for (int mt=0;mt<2;mt++) ldm4(afrag[mt], stg + aBase + mt*(16*ROWB) + kk*2);
#pragma unroll
            for (int p=0;p<2;p++){
                uint32_t r4[4];
                ldm4(r4, stg + bBase + p*(16*ROWB) + kk*2);
                bfrag[2*p][0]=r4[0];   bfrag[2*p][1]=r4[1];
                bfrag[2*p+1][0]=r4[2]; bfrag[2*p+1][1]=r4[3];
            }
#pragma unroll
            for (int mt=0;mt<2;mt++)
#pragma unroll
                for (int nt=0;nt<4;nt++) mma16816(acc[mt][nt], afrag[mt], bfrag[nt]);
        }
        __syncthreads();
    }

    int mb = m0 + warp_m*32;
    int nb = n0 + warp_n*32;
#pragma unroll
    for (int mt=0; mt<2; mt++){
#pragma unroll
        for (int half=0; half<2; half++){
            int m = mb + mt*16 + (lane>>2) + half*8;
#pragma unroll
            for (int nt=0; nt<4; nt++){
                int n = nb + nt*8 + (lane&3)*2;
                float v0 = acc[mt][nt][half*2];
                float v1 = acc[mt][nt][half*2+1];
                size_t idx = (size_t)m*N + n;
                float2 rv = *(const float2*)(res + idx);
                float2 o;
                o.x = v0 + bias[n]   + rv.x;
                o.y = v1 + bias[n+1] + rv.y;
                *(float2*)(outF + idx) = o;
            }
        }
    }
}

// ------------------------- batched weight split (hi only, vectorized) -------
__global__ void __launch_bounds__(256) split_all_kernel(
    const float* __restrict__ Wq, const float* __restrict__ Wk,
    const float* __restrict__ Wv, const float* __restrict__ Wo,
    const float* __restrict__ W1, const float* __restrict__ W2)
{
    int g = blockIdx.x * 256 + threadIdx.x;
    const float* src; __half* dh;
    if (g < 196608){
        int which = g >> 16;
        int j = g & 65535;
        src = (which==0 ? Wq : which==1 ? Wk : Wv) + j*4;
        dh = g_wqkvh + ((size_t)which << 18) + j*4;
    } else if (g < 262144){
        int j = g - 196608; src = Wo + (size_t)j*4; dh = g_woh + (size_t)j*4;
    } else if (g < 524288){
        int j = g - 262144; src = W1 + (size_t)j*4; dh = g_w1h + (size_t)j*4;
    } else {
        int j = g - 524288; src = W2 + (size_t)j*4; dh = g_w2h + (size_t)j*4;
    }
    float4 v = *(const float4*)src;
    uint2 hp;
    hp.x = pack2(v.x, v.y);
    hp.y = pack2(v.z, v.w);
    *(uint2*)dh = hp;
}

// ------------------------- LayerNorm -> fp16 --------------------------------
__global__ void __launch_bounds__(256) ln_h_kernel(
    const float* __restrict__ x, const float* __restrict__ g,
    const float* __restrict__ b, __half* __restrict__ yh)
{
    int row = blockIdx.x;
    const float* xr = x + (size_t)row * D_;
    int tid = threadIdx.x;
    float v0 = xr[tid], v1 = xr[tid + 256];
    float s  = v0 + v1, ss = v0*v0 + v1*v1;
    __shared__ float sh[16];
#pragma unroll
    for (int o = 16; o; o >>= 1) {
        s  += __shfl_xor_sync(0xffffffffu, s,  o);
        ss += __shfl_xor_sync(0xffffffffu, ss, o);
    }
    int w = tid >> 5;
    if ((tid & 31) == 0) { sh[w] = s; sh[w + 8] = ss; }
    __syncthreads();
    float S = 0.f, SS = 0.f;
#pragma unroll
    for (int i = 0; i < 8; i++) { S += sh[i]; SS += sh[8 + i]; }
    float mean = S * (1.0f / D_);
    float rstd = rsqrtf(SS * (1.0f / D_) - mean*mean + 1e-5f);
    size_t base = (size_t)row * D_;
    yh[base + tid]       = __float2half((v0 - mean) * rstd * g[tid]       + b[tid]);
    yh[base + tid + 256] = __float2half((v1 - mean) * rstd * g[tid + 256] + b[tid + 256]);
}

// ---------------------------------------------------------------------------
// Scan level 1 (DUAL direction) — validated R12, unchanged
// ---------------------------------------------------------------------------
__global__ void __launch_bounds__(256) usum_dual_kernel(const float* __restrict__ dlogit)
{
    int bx  = blockIdx.x;
    int j   = bx & 31;
    int bh  = bx >> 5;
    int h   = bh & 7;
    float lam = 1.f / (1.f + expf(-dlogit[h]));

    __shared__ float sK[CH_ * HD_];
    __shared__ float sV[CH_ * HD_];
    __shared__ float wf[CH_], wb[CH_];

    int tid = threadIdx.x;
    if (tid < CH_){
        wf[tid] = powf(lam, (float)(CH_ - 1 - tid));
        wb[tid] = powf(lam, (float)tid);
    }

    int lrow = tid >> 2;
    int lseg = (tid & 3) * 16;
    int pt = j * CH_ + lrow;
    const float* Kg = g_QKV + QKVO     + (size_t)bh * T_ * HD_;
    const float* Vg = g_QKV + 2*QKVO   + (size_t)bh * T_ * HD_;
    {
        const float4* kr = (const float4*)(Kg + (size_t)pt * HD_ + lseg);
        const float4* vr = (const float4*)(Vg + (size_t)pt * HD_ + lseg);
        float4* sk = (float4*)(sK + lrow * HD_ + lseg);
        float4* sv = (float4*)(sV + lrow * HD_ + lseg);
        sk[0]=kr[0]; sk[1]=kr[1]; sk[2]=kr[2]; sk[3]=kr[3];
        sv[0]=vr[0]; sv[1]=vr[1]; sv[2]=vr[2]; sv[3]=vr[3];
    }
    __syncthreads();

    int d = tid & 63, c = tid >> 6;
    int e0 = c * 16;
    float aF[16], aB[16];
#pragma unroll
    for (int i = 0; i < 16; i++){ aF[i] = 0.f; aB[i] = 0.f; }
    float zF = 0.f, zB = 0.f;

#pragma unroll 4
    for (int s = 0; s < CH_; s++){
        float kr = sK[s * HD_ + d];
        float kf = kr * wf[s];
        float kb = kr * wb[s];
        zF += kf; zB += kb;
        const float4* vv = (const float4*)(sV + s * HD_ + e0);
        float4 a0 = vv[0], a1 = vv[1], a2 = vv[2], a3 = vv[3];
        aF[0]=fmaf(kf,a0.x,aF[0]); aB[0]=fmaf(kb,a0.x,aB[0]);
        aF[1]=fmaf(kf,a0.y,aF[1]); aB[1]=fmaf(kb,a0.y,aB[1]);
        aF[2]=fmaf(kf,a0.z,aF[2]); aB[2]=fmaf(kb,a0.z,aB[2]);
        aF[3]=fmaf(kf,a0.w,aF[3]); aB[3]=fmaf(kb,a0.w,aB[3]);
        aF[4]=fmaf(kf,a1.x,aF[4]); aB[4]=fmaf(kb,a1.x,aB[4]);
        aF[5]=fmaf(kf,a1.y,aF[5]); aB[5]=fmaf(kb,a1.y,aB[5]);
        aF[6]=fmaf(kf,a1.z,aF[6]); aB[6]=fmaf(kb,a1.z,aB[6]);
        aF[7]=fmaf(kf,a1.w,aF[7]); aB[7]=fmaf(kb,a1.w,aB[7]);
        aF[8]=fmaf(kf,a2.x,aF[8]); aB[8]=fmaf(kb,a2.x,aB[8]);
        aF[9]=fmaf(kf,a2.y,aF[9]); aB[9]=fmaf(kb,a2.y,aB[9]);
        aF[10]=fmaf(kf,a2.z,aF[10]); aB[10]=fmaf(kb,a2.z,aB[10]);
        aF[11]=fmaf(kf,a2.w,aF[11]); aB[11]=fmaf(kb,a2.w,aB[11]);
        aF[12]=fmaf(kf,a3.x,aF[12]); aB[12]=fmaf(kb,a3.x,aB[12]);
        aF[13]=fmaf(kf,a3.y,aF[13]); aB[13]=fmaf(kb,a3.y,aB[13]);
        aF[14]=fmaf(kf,a3.z,aF[14]); aB[14]=fmaf(kb,a3.z,aB[14]);
        aF[15]=fmaf(kf,a3.w,aF[15]); aB[15]=fmaf(kb,a3.w,aB[15]);
    }

    float* Uf = g_U + (size_t)((0 * NBH_ + bh) * NCH_ + j) * (HD_ * HD_);
    float* Ub = g_U + (size_t)((1 * NBH_ + bh) * NCH_ + (NCH_ - 1 - j)) * (HD_ * HD_);
#pragma unroll
    for (int i = 0; i < 16; i++){
        Uf[(e0 + i) * 64 + d] = aF[i];
        Ub[(e0 + i) * 64 + d] = aB[i];
    }
    if (c == 0){
        g_zU[(size_t)((0 * NBH_ + bh) * NCH_ + j) * HD_ + d] = zF;
        g_zU[(size_t)((1 * NBH_ + bh) * NCH_ + (NCH_ - 1 - j)) * HD_ + d] = zB;
    }
}

// ---------------------------------------------------------------------------
// Scan level 2: sweep — validated, unchanged
// ---------------------------------------------------------------------------
__global__ void __launch_bounds__(256) sweep_kernel(const float* __restrict__ dlogit)
{
    int bx  = blockIdx.x;
    int seg = bx & 15;
    int bh  = (bx >> 4) & 15;
    int dir = bx >> 8;
    int h   = bh & 7;
    float lam  = 1.f / (1.f + expf(-dlogit[h]));
    float lamC = powf(lam, (float)CH_);

    int el = seg * 256 + threadIdx.x;
    size_t base = (size_t)((dir * NBH_ + bh) * NCH_) * (HD_ * HD_);
    float S = 0.f;
#pragma unroll
    for (int jj = 0; jj < NCH_; jj++){
        size_t o = base + (size_t)jj * (HD_ * HD_) + el;
        float u = g_U[o];
        g_Schk[o] = S;
        S = fmaf(lamC, S, u);
    }
    if (seg == 0 && threadIdx.x < HD_){
        int d = threadIdx.x;
        size_t zb = (size_t)((dir * NBH_ + bh) * NCH_) * HD_;
        float z = 0.f;
#pragma unroll
        for (int jj = 0; jj < NCH_; jj++){
            float zu = g_zU[zb + jj * HD_ + d];
            g_zchk[zb + jj * HD_ + d] = z;
            z = fmaf(lamC, z, zu);
        }
    }
}

// ---------------------------------------------------------------------------
// Combined dual-direction chunk kernel + normalize -> fp16 attn output.
// ---------------------------------------------------------------------------
#define COFF_Q   0
#define COFF_K   4160
#define COFF_P   8320
#define COFF_V   12480
#define COFF_SF  16576
#define COFF_SB  20928
#define COFF_ZF  25280
#define COFF_ZB  25344
#define COFF_LP  25408
#define CC_SMEM_BYTES ((25408 + 80) * 4)

__global__ void __launch_bounds__(256) chunk_comb_kernel(const float* __restrict__ dlogit)
{
    extern __shared__ float sm[];
    float* sQ  = sm + COFF_Q;
    float* sK  = sm + COFF_K;
    float* sP  = sm + COFF_P;
    float* sV  = sm + COFF_V;
    float* sSf = sm + COFF_SF;
    float* sSb = sm + COFF_SB;
    float* szf = sm + COFF_ZF;
    float* szb = sm + COFF_ZB;
    float* slp = sm + COFF_LP;

    int bx  = blockIdx.x;
    int j   = bx & 31;
    int bh  = bx >> 5;
    int h   = bh & 7;
    float lam = 1.f / (1.f + expf(-dlogit[h]));

    int tid = threadIdx.x;
    if (tid <= CH_) slp[tid] = powf(lam, (float)tid);

    const float* Qg  = g_QKV            + (size_t)bh * T_ * HD_;
    const float* Kg  = g_QKV + QKVO     + (size_t)bh * T_ * HD_;
    const float* Vg  = g_QKV + 2*QKVO   + (size_t)bh * T_ * HD_;
    const float* Sfin = g_Schk + (size_t)((0 * NBH_ + bh) * NCH_ + j) * (HD_ * HD_);
    const float* Sbin = g_Schk + (size_t)((1 * NBH_ + bh) * NCH_ + (NCH_ - 1 - j)) * (HD_ * HD_);
    const float* zfin = g_zchk + (size_t)((0 * NBH_ + bh) * NCH_ + j) * HD_;
    const float* zbin = g_zchk + (size_t)((1 * NBH_ + bh) * NCH_ + (NCH_ - 1 - j)) * HD_;

    int lrow = tid >> 2;
    int lseg = (tid & 3) * 16;
    int pt0 = j * CH_ + lrow;

#pragma unroll 4
    for (int i = 0; i < 16; i++) {
        sQ[lrow * 65 + lseg + i] = Qg[(size_t)pt0 * HD_ + lseg + i];
        sK[lrow * 65 + lseg + i] = Kg[(size_t)pt0 * HD_ + lseg + i];
    }
    {
        float4* svr = (float4*)(sV + lrow * 64 + lseg);
        const float4* vr = (const float4*)(Vg + (size_t)pt0 * HD_ + lseg);
        svr[0]=vr[0]; svr[1]=vr[1]; svr[2]=vr[2]; svr[3]=vr[3];
    }
#pragma unroll 4
    for (int i = 0; i < 16; i++) {
        int idx = tid * 16 + i;
        int e = idx >> 6, dd = idx & 63;
        sSf[dd * 68 + e] = Sfin[idx];
        sSb[dd * 68 + e] = Sbin[idx];
    }
    if (tid < 64){ szf[tid] = zfin[tid]; szb[tid] = zbin[tid]; }
    __syncthreads();

    {
        int ty = tid >> 4, tx = tid & 15;
        int r0 = ty * 4, c0 = tx * 4;
        float acc[4][4];
#pragma unroll
        for (int i = 0; i < 4; i++)
#pragma unroll
            for (int jc = 0; jc < 4; jc++) acc[i][jc] = 0.f;

        for (int d = 0; d < 64; d++) {
            float q0 = sQ[(r0+0)*65+d], q1 = sQ[(r0+1)*65+d];
            float q2 = sQ[(r0+2)*65+d], q3 = sQ[(r0+3)*65+d];
            float k0 = sK[(c0+0)*65+d], k1 = sK[(c0+1)*65+d];
            float k2 = sK[(c0+2)*65+d], k3 = sK[(c0+3)*65+d];
            acc[0][0]=fmaf(q0,k0,acc[0][0]); acc[0][1]=fmaf(q0,k1,acc[0][1]);
            acc[0][2]=fmaf(q0,k2,acc[0][2]); acc[0][3]=fmaf(q0,k3,acc[0][3]);
            acc[1][0]=fmaf(q1,k0,acc[1][0]); acc[1][1]=fmaf(q1,k1,acc[1][1]);
            acc[1][2]=fmaf(q1,k2,acc[1][2]); acc[1][3]=fmaf(q1,k3,acc[1][3]);
            acc[2][0]=fmaf(q2,k0,acc[2][0]); acc[2][1]=fmaf(q2,k1,acc[2][1]);
            acc[2][2]=fmaf(q2,k2,acc[2][2]); acc[2][3]=fmaf(q2,k3,acc[2][3]);
            acc[3][0]=fmaf(q3,k0,acc[3][0]); acc[3][1]=fmaf(q3,k1,acc[3][1]);
            acc[3][2]=fmaf(q3,k2,acc[3][2]); acc[3][3]=fmaf(q3,k3,acc[3][3]);
        }
#pragma unroll
        for (int i = 0; i < 4; i++) {
            int r = r0 + i;
#pragma unroll
            for (int jc = 0; jc < 4; jc++) {
                int cc = c0 + jc;
                int dlt = r >= cc ? r - cc : cc - r;
                sP[r * 65 + cc] = acc[i][jc] * slp[dlt];
            }
        }
    }
    __syncthreads();

    {
        int rr = (tid >> 3) * 2;
        int c0 = (tid & 7) * 8;
        float aA[2][8], aIf[2][8], aIb[2][8];
#pragma unroll
        for (int i = 0; i < 2; i++)
#pragma unroll
            for (int jc = 0; jc < 8; jc++){ aA[i][jc]=0.f; aIf[i][jc]=0.f; aIb[i][jc]=0.f; }
        float cs0 = 0.f, cs1 = 0.f;
        float cqf0 = 0.f, cqf1 = 0.f, cqb0 = 0.f, cqb1 = 0.f;

        for (int s = 0; s < 64; s++) {
            float a0 = sP[rr * 65 + s];
            float a1 = sP[(rr + 1) * 65 + s];
            cs0 += a0; cs1 += a1;
            float4 v0 = *(const float4*)(sV + s * 64 + c0);
            float4 v1 = *(const float4*)(sV + s * 64 + c0 + 4);
            aA[0][0]=fmaf(a0,v0.x,aA[0][0]); aA[0][1]=fmaf(a0,v0.y,aA[0][1]);
            aA[0][2]=fmaf(a0,v0.z,aA[0][2]); aA[0][3]=fmaf(a0,v0.w,aA[0][3]);
            aA[0][4]=fmaf(a0,v1.x,aA[0][4]); aA[0][5]=fmaf(a0,v1.y,aA[0][5]);
            aA[0][6]=fmaf(a0,v1.z,aA[0][6]); aA[0][7]=fmaf(a0,v1.w,aA[0][7]);
            aA[1][0]=fmaf(a1,v0.x,aA[1][0]); aA[1][1]=fmaf(a1,v0.y,aA[1][1]);
            aA[1][2]=fmaf(a1,v0.z,aA[1][2]); aA[1][3]=fmaf(a1,v0.w,aA[1][3]);
            aA[1][4]=fmaf(a1,v1.x,aA[1][4]); aA[1][5]=fmaf(a1,v1.y,aA[1][5]);
            aA[1][6]=fmaf(a1,v1.z,aA[1][6]); aA[1][7]=fmaf(a1,v1.w,aA[1][7]);
        }
        for (int d = 0; d < 64; d++) {
            float q0 = sQ[rr * 65 + d];
            float q1 = sQ[(rr + 1) * 65 + d];
            cqf0 = fmaf(q0, szf[d], cqf0);
            cqf1 = fmaf(q1, szf[d], cqf1);
            cqb0 = fmaf(q0, szb[d], cqb0);
            cqb1 = fmaf(q1, szb[d], cqb1);
            float4 f0 = *(const float4*)(sSf + d * 68 + c0);
            float4 f1 = *(const float4*)(sSf + d * 68 + c0 + 4);
            float4 b0 = *(const float4*)(sSb + d * 68 + c0);
            float4 b1 = *(const float4*)(sSb + d * 68 + c0 + 4);
            aIf[0][0]=fmaf(q0,f0.x,aIf[0][0]); aIf[0][1]=fmaf(q0,f0.y,aIf[0][1]);
            aIf[0][2]=fmaf(q0,f0.z,aIf[0][2]); aIf[0][3]=fmaf(q0,f0.w,aIf[0][3]);
            aIf[0][4]=fmaf(q0,f1.x,aIf[0][4]); aIf[0][5]=fmaf(q0,f1.y,aIf[0][5]);
            aIf[0][6]=fmaf(q0,f1.z,aIf[0][6]); aIf[0][7]=fmaf(q0,f1.w,aIf[0][7]);
            aIf[1][0]=fmaf(q1,f0.x,aIf[1][0]); aIf[1][1]=fmaf(q1,f0.y,aIf[1][1]);
            aIf[1][2]=fmaf(q1,f0.z,aIf[1][2]); aIf[1][3]=fmaf(q1,f0.w,aIf[1][3]);
            aIf[1][4]=fmaf(q1,f1.x,aIf[1][4]); aIf[1][5]=fmaf(q1,f1.y,aIf[1][5]);
            aIf[1][6]=fmaf(q1,f1.z,aIf[1][6]); aIf[1][7]=fmaf(q1,f1.w,aIf[1][7]);
            aIb[0][0]=fmaf(q0,b0.x,aIb[0][0]); aIb[0][1]=fmaf(q0,b0.y,aIb[0][1]);
            aIb[0][2]=fmaf(q0,b0.z,aIb[0][2]); aIb[0][3]=fmaf(q0,b0.w,aIb[0][3]);
            aIb[0][4]=fmaf(q0,b1.x,aIb[0][4]); aIb[0][5]=fmaf(q0,b1.y,aIb[0][5]);
            aIb[0][6]=fmaf(q0,b1.z,aIb[0][6]); aIb[0][7]=fmaf(q0,b1.w,aIb[0][7]);
            aIb[1][0]=fmaf(q1,b0.x,aIb[1][0]); aIb[1][1]=fmaf(q1,b0.y,aIb[1][1]);
            aIb[1][2]=fmaf(q1,b0.z,aIb[1][2]); aIb[1][3]=fmaf(q1,b0.w,aIb[1][3]);
            aIb[1][4]=fmaf(q1,b1.x,aIb[1][4]); aIb[1][5]=fmaf(q1,b1.y,aIb[1][5]);
            aIb[1][6]=fmaf(q1,b1.z,aIb[1][6]); aIb[1][7]=fmaf(q1,b1.w,aIb[1][7]);
        }

        int b = bh >> 3;
#pragma unroll
        for (int i = 0; i < 2; i++) {
            int r = rr + i;
            int t = j * CH_ + r;
            float lf = slp[r + 1];
            float lb = slp[CH_ - r];
            float cden = (i ? cs1 : cs0)
                       + lf * (i ? cqf1 : cqf0)
                       + lb * (i ? cqb1 : cqb0);
            float inv = 1.f / fmaxf(cden, 1e-6f);
            uint32_t hp[4];
#pragma unroll
            for (int u = 0; u < 4; u++){
                float y0 = (aA[i][2*u]   + lf*aIf[i][2*u]   + lb*aIb[i][2*u]  ) * inv;
                float y1 = (aA[i][2*u+1] + lf*aIf[i][2*u+1] + lb*aIb[i][2*u+1]) * inv;
                hp[u] = pack2(y0, y1);
            }
            size_t dst = ((size_t)(b * T_ + t) * D_) + h * HD_ + c0;
            *(uint4*)(g_ath + dst) = make_uint4(hp[0], hp[1], hp[2], hp[3]);
        }
    }
}

// ------------------------- launcher ----------------------------------------
extern "C" void kernel_launch(void* const* d_in, const int* in_sizes, int n_in,
                              void* d_out, int out_size)
{
    const float* x    = (const float*)d_in[0];
    const float* Wq   = (const float*)d_in[2];
    const float* Wk   = (const float*)d_in[3];
    const float* Wv   = (const float*)d_in[4];
    const float* Wo   = (const float*)d_in[5];
    const float* bo   = (const float*)d_in[6];
    const float* g1   = (const float*)d_in[7];
    const float* b1   = (const float*)d_in[8];
    const float* g2   = (const float*)d_in[9];
    const float* b2   = (const float*)d_in[10];
    const float* W1   = (const float*)d_in[11];
    const float* bf1  = (const float*)d_in[12];
    const float* W2   = (const float*)d_in[13];
    const float* bf2  = (const float*)d_in[14];
    const float* dlog = (const float*)d_in[15];
    float* out = (float*)d_out;

#define SYM(p, s) cudaGetSymbolAddress((void**)&p, s)
    __half *xnh,*ath,*h2h,*f1h;
    __half *wqkvh,*woh,*w1h,*w2h;
    float *QKV,*x2;
    SYM(xnh,g_xnh); SYM(ath,g_ath); SYM(h2h,g_h2h); SYM(f1h,g_f1h);
    SYM(wqkvh,g_wqkvh); SYM(woh,g_woh); SYM(w1h,g_w1h); SYM(w2h,g_w2h);
    SYM(QKV,g_QKV); SYM(x2,g_x2);
#undef SYM

    cudaFuncSetAttribute(tc_gemm<4,512>,   cudaFuncAttributeMaxDynamicSharedMemorySize, GEMM_SMEM);
    cudaFuncSetAttribute(tc_gemm<3,512>,   cudaFuncAttributeMaxDynamicSharedMemorySize, GEMM_SMEM);
    cudaFuncSetAttribute(tc_gemm64<512>,   cudaFuncAttributeMaxDynamicSharedMemorySize, GEMM64_SMEM);
    cudaFuncSetAttribute(tc_gemm64<2048>,  cudaFuncAttributeMaxDynamicSharedMemorySize, GEMM64_SMEM);
    cudaFuncSetAttribute(chunk_comb_kernel,cudaFuncAttributeMaxDynamicSharedMemorySize, CC_SMEM_BYTES);

    dim3 blk(256);
    dim3 gQKV((3*D_) / 128, M_ / 128);  // (12, 32) = 384 CTAs
    dim3 gD64(D_ / 128, M_ / 64);       // (4, 64)  = 256 CTAs
    dim3 gF(F_ / 128, M_ / 128);        // (16, 32) = 512 CTAs

    // 0) all weight conversions, one launch
    split_all_kernel<<<786432/256, blk>>>(Wq, Wk, Wv, Wo, W1, W2);
    // 1) LN1 -> fp16
    ln_h_kernel<<<M_, blk>>>(x, g1, b1, xnh);
    // 2) fused Q/K/V projection (single-pass fp16)
    tc_gemm<4,512><<<gQKV, blk, GEMM_SMEM>>>(xnh, wqkvh, 3*D_, nullptr, QKV, nullptr);
    // 3) dual-direction two-level scan + fused chunk/combine -> fp16 attn
    usum_dual_kernel<<<NBH_ * NCH_, blk>>>(dlog);
    sweep_kernel<<<2 * NBH_ * 16, blk>>>(dlog);
    chunk_comb_kernel<<<NBH_ * NCH_, blk, CC_SMEM_BYTES>>>(dlog);
    // 4) Wo + bias + residual -> fp32 x2
    tc_gemm64<512><<<gD64, blk, GEMM64_SMEM>>>(ath, woh, D_, bo, x, x2);
    // 5) LN2 -> fp16
    ln_h_kernel<<<M_, blk>>>(x2, g2, b2, h2h);
    // 6) FFN up + GELU -> fp16
    tc_gemm<3,512><<<gF, blk, GEMM_SMEM>>>(h2h, w1h, F_, bf1, nullptr, f1h);
    // 7) FFN down + bias + residual -> final output
    tc_gemm64<2048><<<gD64, blk, GEMM64_SMEM>>>(f1h, w2h, D_, bf2, x2, out);
}

// round 17
// speedup vs baseline: 1.4704x; 1.0334x over previous
#include <cuda_runtime.h>
#include <cuda_fp16.h>
#include <math.h>
#include <stdint.h>

#define B_   2
#define T_   2048
#define D_   512
#define H_   8
#define HD_  64
#define F_   2048
#define M_   (B_*T_)
#define CH_  64
#define NCH_ (T_/CH_)
#define NBH_ (B_*H_)
#define QKVO (NBH_*T_*HD_)

// ------------------------- scratch globals ---------------------------------
__device__ __half g_xnh[M_*D_];
__device__ __half g_ath[M_*D_];
__device__ __half g_h2h[M_*D_];
__device__ __half g_f1h[M_*F_];
__device__ __half g_wqkvh[3*D_*D_];          // Wq|Wk|Wv rows
__device__ __half g_woh[D_*D_];
__device__ __half g_w1h[F_*D_];
__device__ __half g_w2h[D_*F_];
__device__ __half g_QKV[3*QKVO];             // Q|K|V [b,h,t,e]  (fp16)
__device__ float g_x2[M_*D_];
__device__ float g_Schk[2*NBH_*NCH_*HD_*HD_];
__device__ float g_zchk[2*NBH_*NCH_*HD_];
__device__ float g_U   [2*NBH_*NCH_*HD_*HD_];
__device__ float g_zU  [2*NBH_*NCH_*HD_];

// ------------------------- helpers -----------------------------------------
static __device__ __forceinline__ uint32_t stou(const void* p){
    uint32_t a;
    asm("{ .reg .u64 t; cvta.to.shared.u64 t, %1; cvt.u32.u64 %0, t; }" : "=r"(a) : "l"(p));
    return a;
}
static __device__ __forceinline__ void cp16(uint32_t dst, const void* src){
    asm volatile("cp.async.cg.shared.global [%0], [%1], 16;" :: "r"(dst), "l"(src));
}
static __device__ __forceinline__ void ldm4(uint32_t* a, uint32_t addr){
    asm volatile("ldmatrix.sync.aligned.m8n8.x4.shared.b16 {%0,%1,%2,%3}, [%4];"
        : "=r"(a[0]),"=r"(a[1]),"=r"(a[2]),"=r"(a[3]) : "r"(addr));
}
static __device__ __forceinline__ void mma16816(float* c, const uint32_t* a, const uint32_t* b){
    asm volatile("mma.sync.aligned.m16n8k16.row.col.f32.f16.f16.f32 "
        "{%0,%1,%2,%3}, {%4,%5,%6,%7}, {%8,%9}, {%0,%1,%2,%3};"
        : "+f"(c[0]),"+f"(c[1]),"+f"(c[2]),"+f"(c[3])
        : "r"(a[0]),"r"(a[1]),"r"(a[2]),"r"(a[3]), "r"(b[0]),"r"(b[1]));
}
static __device__ __forceinline__ uint32_t pack2(float a, float b){
    return (uint32_t)__half_as_ushort(__float2half(a)) |
           ((uint32_t)__half_as_ushort(__float2half(b)) << 16);
}
// unpack uint4 (8 halves) -> 8 floats
static __device__ __forceinline__ void h8f(uint4 v, float* o){
    float2 f;
    f = __half22float2(*(__half2*)&v.x); o[0]=f.x; o[1]=f.y;
    f = __half22float2(*(__half2*)&v.y); o[2]=f.x; o[3]=f.y;
    f = __half22float2(*(__half2*)&v.z); o[4]=f.x; o[5]=f.y;
    f = __half22float2(*(__half2*)&v.w); o[6]=f.x; o[7]=f.y;
}

#define ROWB  144
#define ATILE 18432
#define STGB  36864
#define GEMM_SMEM (3*STGB)          // 3-stage
#define BOFF64  9216
#define STGB64  27648
#define GEMM64_SMEM (2*STGB64)

// ---------------------------------------------------------------------------
// 128x128 fp16 GEMM, 3-stage, single barrier/iter, 8 warps, warp tile 64x32.
// MODE: 3=bias+gelu->fp16   4=fused QKV scatter (elu for n<1024) -> fp16
// ---------------------------------------------------------------------------
template<int MODE, int KDIM>
__global__ void __launch_bounds__(256,2) tc_gemm(
    const __half* __restrict__ Ah, const __half* __restrict__ Bh,
    int N, const float* __restrict__ bias, __half* __restrict__ outH)
{
    extern __shared__ char dyns[];
    uint32_t sb = stou(dyns);

    int tid = threadIdx.x;
    int lane = tid & 31, w = tid >> 5;
    int warp_m = w >> 2, warp_n = w & 3;
    int m0 = blockIdx.y * 128;
    int n0 = blockIdx.x * 128;

    float acc[4][4][4];
#pragma unroll
    for (int i=0;i<4;i++)
#pragma unroll
        for (int j=0;j<4;j++)
#pragma unroll
            for (int k=0;k<4;k++) acc[i][j][k] = 0.f;

    const int NIT = KDIM/64;

    auto fill = [&](int itf){
        int st = itf % 3;
        int koff = itf * 64;
        uint32_t base = sb + st*STGB;
#pragma unroll
        for (int i=0;i<8;i++){
            int q = tid + i*256;
            int isB = q >> 10;
            int r   = (q >> 3) & 127;
            int c16 = q & 7;
            const __half* src =
                (isB ? (Bh + (size_t)(n0+r)*KDIM) : (Ah + (size_t)(m0+r)*KDIM)) + koff + c16*8;
            cp16(base + isB*ATILE + r*ROWB + c16*16, src);
        }
        asm volatile("cp.async.commit_group;" ::: "memory");
    };

    uint32_t aBase = (uint32_t)((warp_m*64 + (lane & 15))*ROWB + ((lane >> 4) << 4));
    uint32_t bBase = (uint32_t)(ATILE +
        (warp_n*32 + ((lane >> 4) << 3) + (lane & 7))*ROWB + (((lane >> 3) & 1) << 4));

    fill(0);
    if (NIT > 1) fill(1);
    for (int it=0; it<NIT; ++it){
        if (it+1 < NIT) asm volatile("cp.async.wait_group 1;" ::: "memory");
        else            asm volatile("cp.async.wait_group 0;" ::: "memory");
        __syncthreads();
        if (it+2 < NIT) fill(it+2);     // stage (it+2)%3: last read at it-1, all warps past sync
        uint32_t stg = sb + (it%3)*STGB;
#pragma unroll
        for (int kk=0; kk<64; kk+=16){
            uint32_t afrag[4][4], bfrag[4][2];
#pragma unroll
            for (int mt=0;mt<4;mt++) ldm4(afrag[mt], stg + aBase + mt*(16*ROWB) + kk*2);
#pragma unroll
            for (int p=0;p<2;p++){
                uint32_t r4[4];
                ldm4(r4, stg + bBase + p*(16*ROWB) + kk*2);
                bfrag[2*p][0]=r4[0];   bfrag[2*p][1]=r4[1];
                bfrag[2*p+1][0]=r4[2]; bfrag[2*p+1][1]=r4[3];
            }
#pragma unroll
            for (int mt=0;mt<4;mt++)
#pragma unroll
                for (int nt=0;nt<4;nt++) mma16816(acc[mt][nt], afrag[mt], bfrag[nt]);
        }
    }

    int mb = m0 + warp_m*64;
    int nb = n0 + warp_n*32;
#pragma unroll
    for (int mt=0; mt<4; mt++){
#pragma unroll
        for (int half=0; half<2; half++){
            int m = mb + mt*16 + (lane>>2) + half*8;
            int bb = m >> 11, tt = m & (T_-1);
#pragma unroll
            for (int nt=0; nt<4; nt++){
                int n = nb + nt*8 + (lane&3)*2;
                float v0 = acc[mt][nt][half*2];
                float v1 = acc[mt][nt][half*2+1];
                if (MODE == 4){
                    int mat = n >> 9;              // 0=Q 1=K 2=V
                    if (mat < 2){
                        v0 = v0>0.f ? v0+1.f : expf(v0);
                        v1 = v1>0.f ? v1+1.f : expf(v1);
                    }
                    int hh = (n >> 6) & 7, ee = n & 63;
                    __half* dst = g_QKV + (size_t)mat*QKVO
                                + ((((size_t)(bb*H_ + hh))*T_ + tt)<<6) + ee;
                    *(uint32_t*)dst = pack2(v0, v1);
                } else {   // MODE 3: bias + exact GELU -> fp16
                    size_t idx = (size_t)m*N + n;
                    float a = v0 + bias[n];
                    float b = v1 + bias[n+1];
                    a = 0.5f*a*(1.f+erff(a*0.70710678118654752f));
                    b = 0.5f*b*(1.f+erff(b*0.70710678118654752f));
                    *(uint32_t*)(outH + idx) = pack2(a, b);
                }
            }
        }
    }
}

// ---------------------------------------------------------------------------
// 64x128 fp16 GEMM (single pass), 2-stage, 3 CTAs/SM. bias+res -> fp32.
// ---------------------------------------------------------------------------
template<int KDIM>
__global__ void __launch_bounds__(256,3) tc_gemm64(
    const __half* __restrict__ Ah, const __half* __restrict__ Bh,
    int N, const float* __restrict__ bias, const float* __restrict__ res,
    float* __restrict__ outF)
{
    extern __shared__ char dyns[];
    uint32_t sb = stou(dyns);

    int tid = threadIdx.x;
    int lane = tid & 31, w = tid >> 5;
    int warp_m = w >> 2, warp_n = w & 3;
    int m0 = blockIdx.y * 64;
    int n0 = blockIdx.x * 128;

    float acc[2][4][4];
#pragma unroll
    for (int i=0;i<2;i++)
#pragma unroll
        for (int j=0;j<4;j++)
#pragma unroll
            for (int k=0;k<4;k++) acc[i][j][k] = 0.f;

    const int NIT = KDIM/64;

    auto fill = [&](int itf){
        int st = itf & 1;
        int koff = itf * 64;
        uint32_t base = sb + st*STGB64;
#pragma unroll
        for (int i=0;i<6;i++){
            int q = tid + i*256;
            if (q < 512){
                int r = q >> 3, c16 = q & 7;
                cp16(base + r*ROWB + c16*16,
                     Ah + (size_t)(m0+r)*KDIM + koff + c16*8);
            } else {
                int q2 = q - 512;
                int r = q2 >> 3, c16 = q2 & 7;
                cp16(base + BOFF64 + r*ROWB + c16*16,
                     Bh + (size_t)(n0+r)*KDIM + koff + c16*8);
            }
        }
        asm volatile("cp.async.commit_group;" ::: "memory");
    };

    uint32_t aBase = (uint32_t)((warp_m*32 + (lane & 15))*ROWB + ((lane >> 4) << 4));
    uint32_t bBase = (uint32_t)(BOFF64 +
        (warp_n*32 + ((lane >> 4) << 3) + (lane & 7))*ROWB + (((lane >> 3) & 1) << 4));

    fill(0);
    for (int it=0; it<NIT; ++it){
        if (it+1 < NIT){
            fill(it+1);
            asm volatile("cp.async.wait_group 1;" ::: "memory");
        } else {
            asm volatile("cp.async.wait_group 0;" ::: "memory");
        }
        __syncthreads();
        uint32_t stg = sb + (it&1)*STGB64;
#pragma unroll
        for (int kk=0; kk<64; kk+=16){
            uint32_t afrag[2][4], bfrag[4][2];
#pragma unroll
            for (int mt=0;mt<2;mt++) ldm4(afrag[mt], stg + aBase + mt*(16*ROWB) + kk*2);
#pragma unroll
            for (int p=0;p<2;p++){
                uint32_t r4[4];
                ldm4(r4, stg + bBase + p*(16*ROWB) + kk*2);
                bfrag[2*p][0]=r4[0];   bfrag[2*p][1]=r4[1];
                bfrag[2*p+1][0]=r4[2]; bfrag[2*p+1][1]=r4[3];
            }
#pragma unroll
            for (int mt=0;mt<2;mt++)
#pragma unroll
                for (int nt=0;nt<4;nt++) mma16816(acc[mt][nt], afrag[mt], bfrag[nt]);
        }
        __syncthreads();
    }

    int mb = m0 + warp_m*32;
    int nb = n0 + warp_n*32;
#pragma unroll
    for (int mt=0; mt<2; mt++){
#pragma unroll
        for (int half=0; half<2; half++){
            int m = mb + mt*16 + (lane>>2) + half*8;
#pragma unroll
            for (int nt=0; nt<4; nt++){
                int n = nb + nt*8 + (lane&3)*2;
                float v0 = acc[mt][nt][half*2];
                float v1 = acc[mt][nt][half*2+1];
                size_t idx = (size_t)m*N + n;
                float2 rv = *(const float2*)(res + idx);
                float2 o;
                o.x = v0 + bias[n]   + rv.x;
                o.y = v1 + bias[n+1] + rv.y;
                *(float2*)(outF + idx) = o;
            }
        }
    }
}

// ------------------------- batched weight convert ---------------------------
__global__ void __launch_bounds__(256) split_all_kernel(
    const float* __restrict__ Wq, const float* __restrict__ Wk,
    const float* __restrict__ Wv, const float* __restrict__ Wo,
    const float* __restrict__ W1, const float* __restrict__ W2)
{
    int g = blockIdx.x * 256 + threadIdx.x;
    const float* src; __half* dh;
    if (g < 196608){
        int which = g >> 16;
        int j = g & 65535;
        src = (which==0 ? Wq : which==1 ? Wk : Wv) + j*4;
        dh = g_wqkvh + ((size_t)which << 18) + j*4;
    } else if (g < 262144){
        int j = g - 196608; src = Wo + (size_t)j*4; dh = g_woh + (size_t)j*4;
    } else if (g < 524288){
        int j = g - 262144; src = W1 + (size_t)j*4; dh = g_w1h + (size_t)j*4;
    } else {
        int j = g - 524288; src = W2 + (size_t)j*4; dh = g_w2h + (size_t)j*4;
    }
    float4 v = *(const float4*)src;
    uint2 hp;
    hp.x = pack2(v.x, v.y);
    hp.y = pack2(v.z, v.w);
    *(uint2*)dh = hp;
}

// ------------------------- LayerNorm -> fp16 --------------------------------
__global__ void __launch_bounds__(256) ln_h_kernel(
    const float* __restrict__ x, const float* __restrict__ g,
    const float* __restrict__ b, __half* __restrict__ yh)
{
    int row = blockIdx.x;
    const float* xr = x + (size_t)row * D_;
    int tid = threadIdx.x;
    float v0 = xr[tid], v1 = xr[tid + 256];
    float s  = v0 + v1, ss = v0*v0 + v1*v1;
    __shared__ float sh[16];
#pragma unroll
    for (int o = 16; o; o >>= 1) {
        s  += __shfl_xor_sync(0xffffffffu, s,  o);
        ss += __shfl_xor_sync(0xffffffffu, ss, o);
    }
    int w = tid >> 5;
    if ((tid & 31) == 0) { sh[w] = s; sh[w + 8] = ss; }
    __syncthreads();
    float S = 0.f, SS = 0.f;
#pragma unroll
    for (int i = 0; i < 8; i++) { S += sh[i]; SS += sh[8 + i]; }
    float mean = S * (1.0f / D_);
    float rstd = rsqrtf(SS * (1.0f / D_) - mean*mean + 1e-5f);
    size_t base = (size_t)row * D_;
    yh[base + tid]       = __float2half((v0 - mean) * rstd * g[tid]       + b[tid]);
    yh[base + tid + 256] = __float2half((v1 - mean) * rstd * g[tid + 256] + b[tid + 256]);
}

// ---------------------------------------------------------------------------
// Scan level 1 (DUAL direction) — fp16 K/V loads, fp32 math (as R12)
// ---------------------------------------------------------------------------
__global__ void __launch_bounds__(256) usum_dual_kernel(const float* __restrict__ dlogit)
{
    int bx  = blockIdx.x;
    int j   = bx & 31;
    int bh  = bx >> 5;
    int h   = bh & 7;
    float lam = 1.f / (1.f + expf(-dlogit[h]));

    __shared__ float sK[CH_ * HD_];
    __shared__ float sV[CH_ * HD_];
    __shared__ float wf[CH_], wb[CH_];

    int tid = threadIdx.x;
    if (tid < CH_){
        wf[tid] = powf(lam, (float)(CH_ - 1 - tid));
        wb[tid] = powf(lam, (float)tid);
    }

    int lrow = tid >> 2;
    int lseg = (tid & 3) * 16;
    int pt = j * CH_ + lrow;
    const __half* Kg = g_QKV + QKVO     + (size_t)bh * T_ * HD_;
    const __half* Vg = g_QKV + 2*QKVO   + (size_t)bh * T_ * HD_;
    {
        const uint4* kr = (const uint4*)(Kg + (size_t)pt * HD_ + lseg);
        const uint4* vr = (const uint4*)(Vg + (size_t)pt * HD_ + lseg);
        float kf[16], vf[16];
        h8f(kr[0], kf); h8f(kr[1], kf+8);
        h8f(vr[0], vf); h8f(vr[1], vf+8);
        float4* sk = (float4*)(sK + lrow * HD_ + lseg);
        float4* sv = (float4*)(sV + lrow * HD_ + lseg);
#pragma unroll
        for (int i=0;i<4;i++){
            sk[i] = make_float4(kf[4*i],kf[4*i+1],kf[4*i+2],kf[4*i+3]);
            sv[i] = make_float4(vf[4*i],vf[4*i+1],vf[4*i+2],vf[4*i+3]);
        }
    }
    __syncthreads();

    int d = tid & 63, c = tid >> 6;
    int e0 = c * 16;
    float aF[16], aB[16];
#pragma unroll
    for (int i = 0; i < 16; i++){ aF[i] = 0.f; aB[i] = 0.f; }
    float zF = 0.f, zB = 0.f;

#pragma unroll 4
    for (int s = 0; s < CH_; s++){
        float kr = sK[s * HD_ + d];
        float kf = kr * wf[s];
        float kb = kr * wb[s];
        zF += kf; zB += kb;
        const float4* vv = (const float4*)(sV + s * HD_ + e0);
        float4 a0 = vv[0], a1 = vv[1], a2 = vv[2], a3 = vv[3];
        aF[0]=fmaf(kf,a0.x,aF[0]); aB[0]=fmaf(kb,a0.x,aB[0]);
        aF[1]=fmaf(kf,a0.y,aF[1]); aB[1]=fmaf(kb,a0.y,aB[1]);
        aF[2]=fmaf(kf,a0.z,aF[2]); aB[2]=fmaf(kb,a0.z,aB[2]);
        aF[3]=fmaf(kf,a0.w,aF[3]); aB[3]=fmaf(kb,a0.w,aB[3]);
        aF[4]=fmaf(kf,a1.x,aF[4]); aB[4]=fmaf(kb,a1.x,aB[4]);
        aF[5]=fmaf(kf,a1.y,aF[5]); aB[5]=fmaf(kb,a1.y,aB[5]);
        aF[6]=fmaf(kf,a1.z,aF[6]); aB[6]=fmaf(kb,a1.z,aB[6]);
        aF[7]=fmaf(kf,a1.w,aF[7]); aB[7]=fmaf(kb,a1.w,aB[7]);
        aF[8]=fmaf(kf,a2.x,aF[8]); aB[8]=fmaf(kb,a2.x,aB[8]);
        aF[9]=fmaf(kf,a2.y,aF[9]); aB[9]=fmaf(kb,a2.y,aB[9]);
        aF[10]=fmaf(kf,a2.z,aF[10]); aB[10]=fmaf(kb,a2.z,aB[10]);
        aF[11]=fmaf(kf,a2.w,aF[11]); aB[11]=fmaf(kb,a2.w,aB[11]);
        aF[12]=fmaf(kf,a3.x,aF[12]); aB[12]=fmaf(kb,a3.x,aB[12]);
        aF[13]=fmaf(kf,a3.y,aF[13]); aB[13]=fmaf(kb,a3.y,aB[13]);
        aF[14]=fmaf(kf,a3.z,aF[14]); aB[14]=fmaf(kb,a3.z,aB[14]);
        aF[15]=fmaf(kf,a3.w,aF[15]); aB[15]=fmaf(kb,a3.w,aB[15]);
    }

    float* Uf = g_U + (size_t)((0 * NBH_ + bh) * NCH_ + j) * (HD_ * HD_);
    float* Ub = g_U + (size_t)((1 * NBH_ + bh) * NCH_ + (NCH_ - 1 - j)) * (HD_ * HD_);
#pragma unroll
    for (int i = 0; i < 16; i++){
        Uf[(e0 + i) * 64 + d] = aF[i];
        Ub[(e0 + i) * 64 + d] = aB[i];
    }
    if (c == 0){
        g_zU[(size_t)((0 * NBH_ + bh) * NCH_ + j) * HD_ + d] = zF;
        g_zU[(size_t)((1 * NBH_ + bh) * NCH_ + (NCH_ - 1 - j)) * HD_ + d] = zB;
    }
}

// ---------------------------------------------------------------------------
// Scan level 2: sweep — validated, unchanged
// ---------------------------------------------------------------------------
__global__ void __launch_bounds__(256) sweep_kernel(const float* __restrict__ dlogit)
{
    int bx  = blockIdx.x;
    int seg = bx & 15;
    int bh  = (bx >> 4) & 15;
    int dir = bx >> 8;
    int h   = bh & 7;
    float lam  = 1.f / (1.f + expf(-dlogit[h]));
    float lamC = powf(lam, (float)CH_);

    int el = seg * 256 + threadIdx.x;
    size_t base = (size_t)((dir * NBH_ + bh) * NCH_) * (HD_ * HD_);
    float S = 0.f;
#pragma unroll
    for (int jj = 0; jj < NCH_; jj++){
        size_t o = base + (size_t)jj * (HD_ * HD_) + el;
        float u = g_U[o];
        g_Schk[o] = S;
        S = fmaf(lamC, S, u);
    }
    if (seg == 0 && threadIdx.x < HD_){
        int d = threadIdx.x;
        size_t zb = (size_t)((dir * NBH_ + bh) * NCH_) * HD_;
        float z = 0.f;
#pragma unroll
        for (int jj = 0; jj < NCH_; jj++){
            float zu = g_zU[zb + jj * HD_ + d];
            g_zchk[zb + jj * HD_ + d] = z;
            z = fmaf(lamC, z, zu);
        }
    }
}

// ---------------------------------------------------------------------------
// Combined dual-direction chunk kernel + normalize -> fp16 attn output.
// fp16 Q/K/V loads, fp32 math otherwise identical to R16.
// ---------------------------------------------------------------------------
#define COFF_Q   0
#define COFF_K   4160
#define COFF_P   8320
#define COFF_V   12480
#define COFF_SF  16576
#define COFF_SB  20928
#define COFF_ZF  25280
#define COFF_ZB  25344
#define COFF_LP  25408
#define CC_SMEM_BYTES ((25408 + 80) * 4)

__global__ void __launch_bounds__(256) chunk_comb_kernel(const float* __restrict__ dlogit)
{
    extern __shared__ float sm[];
    float* sQ  = sm + COFF_Q;
    float* sK  = sm + COFF_K;
    float* sP  = sm + COFF_P;
    float* sV  = sm + COFF_V;
    float* sSf = sm + COFF_SF;
    float* sSb = sm + COFF_SB;
    float* szf = sm + COFF_ZF;
    float* szb = sm + COFF_ZB;
    float* slp = sm + COFF_LP;

    int bx  = blockIdx.x;
    int j   = bx & 31;
    int bh  = bx >> 5;
    int h   = bh & 7;
    float lam = 1.f / (1.f + expf(-dlogit[h]));

    int tid = threadIdx.x;
    if (tid <= CH_) slp[tid] = powf(lam, (float)tid);

    const __half* Qg  = g_QKV            + (size_t)bh * T_ * HD_;
    const __half* Kg  = g_QKV + QKVO     + (size_t)bh * T_ * HD_;
    const __half* Vg  = g_QKV + 2*QKVO   + (size_t)bh * T_ * HD_;
    const float* Sfin = g_Schk + (size_t)((0 * NBH_ + bh) * NCH_ + j) * (HD_ * HD_);
    const float* Sbin = g_Schk + (size_t)((1 * NBH_ + bh) * NCH_ + (NCH_ - 1 - j)) * (HD_ * HD_);
    const float* zfin = g_zchk + (size_t)((0 * NBH_ + bh) * NCH_ + j) * HD_;
    const float* zbin = g_zchk + (size_t)((1 * NBH_ + bh) * NCH_ + (NCH_ - 1 - j)) * HD_;

    int lrow = tid >> 2;
    int lseg = (tid & 3) * 16;
    int pt0 = j * CH_ + lrow;

    {
        const uint4* qr = (const uint4*)(Qg + (size_t)pt0 * HD_ + lseg);
        const uint4* kr = (const uint4*)(Kg + (size_t)pt0 * HD_ + lseg);
        const uint4* vr = (const uint4*)(Vg + (size_t)pt0 * HD_ + lseg);
        float qf[16], kf[16], vf[16];
        h8f(qr[0], qf); h8f(qr[1], qf+8);
        h8f(kr[0], kf); h8f(kr[1], kf+8);
        h8f(vr[0], vf); h8f(vr[1], vf+8);
#pragma unroll
        for (int i = 0; i < 16; i++) {
            sQ[lrow * 65 + lseg + i] = qf[i];
            sK[lrow * 65 + lseg + i] = kf[i];
        }
        float4* svr = (float4*)(sV + lrow * 64 + lseg);
#pragma unroll
        for (int i = 0; i < 4; i++)
            svr[i] = make_float4(vf[4*i],vf[4*i+1],vf[4*i+2],vf[4*i+3]);
    }
#pragma unroll 4
    for (int i = 0; i < 16; i++) {
        int idx = tid * 16 + i;
        int e = idx >> 6, dd = idx & 63;
        sSf[dd * 68 + e] = Sfin[idx];
        sSb[dd * 68 + e] = Sbin[idx];
    }
    if (tid < 64){ szf[tid] = zfin[tid]; szb[tid] = zbin[tid]; }
    __syncthreads();

    {
        int ty = tid >> 4, tx = tid & 15;
        int r0 = ty * 4, c0 = tx * 4;
        float acc[4][4];
#pragma unroll
        for (int i = 0; i < 4; i++)
#pragma unroll
            for (int jc = 0; jc < 4; jc++) acc[i][jc] = 0.f;

        for (int d = 0; d < 64; d++) {
            float q0 = sQ[(r0+0)*65+d], q1 = sQ[(r0+1)*65+d];
            float q2 = sQ[(r0+2)*65+d], q3 = sQ[(r0+3)*65+d];
            float k0 = sK[(c0+0)*65+d], k1 = sK[(c0+1)*65+d];
            float k2 = sK[(c0+2)*65+d], k3 = sK[(c0+3)*65+d];
            acc[0][0]=fmaf(q0,k0,acc[0][0]); acc[0][1]=fmaf(q0,k1,acc[0][1]);
            acc[0][2]=fmaf(q0,k2,acc[0][2]); acc[0][3]=fmaf(q0,k3,acc[0][3]);
            acc[1][0]=fmaf(q1,k0,acc[1][0]); acc[1][1]=fmaf(q1,k1,acc[1][1]);
            acc[1][2]=fmaf(q1,k2,acc[1][2]); acc[1][3]=fmaf(q1,k3,acc[1][3]);
            acc[2][0]=fmaf(q2,k0,acc[2][0]); acc[2][1]=fmaf(q2,k1,acc[2][1]);
            acc[2][2]=fmaf(q2,k2,acc[2][2]); acc[2][3]=fmaf(q2,k3,acc[2][3]);
            acc[3][0]=fmaf(q3,k0,acc[3][0]); acc[3][1]=fmaf(q3,k1,acc[3][1]);
            acc[3][2]=fmaf(q3,k2,acc[3][2]); acc[3][3]=fmaf(q3,k3,acc[3][3]);
        }
#pragma unroll
        for (int i = 0; i < 4; i++) {
            int r = r0 + i;
#pragma unroll
            for (int jc = 0; jc < 4; jc++) {
                int cc = c0 + jc;
                int dlt = r >= cc ? r - cc : cc - r;
                sP[r * 65 + cc] = acc[i][jc] * slp[dlt];
            }
        }
    }
    __syncthreads();

    {
        int rr = (tid >> 3) * 2;
        int c0 = (tid & 7) * 8;
        float aA[2][8], aIf[2][8], aIb[2][8];
#pragma unroll
        for (int i = 0; i < 2; i++)
#pragma unroll
            for (int jc = 0; jc < 8; jc++){ aA[i][jc]=0.f; aIf[i][jc]=0.f; aIb[i][jc]=0.f; }
        float cs0 = 0.f, cs1 = 0.f;
        float cqf0 = 0.f, cqf1 = 0.f, cqb0 = 0.f, cqb1 = 0.f;

        for (int s = 0; s < 64; s++) {
            float a0 = sP[rr * 65 + s];
            float a1 = sP[(rr + 1) * 65 + s];
            cs0 += a0; cs1 += a1;
            float4 v0 = *(const float4*)(sV + s * 64 + c0);
            float4 v1 = *(const float4*)(sV + s * 64 + c0 + 4);
            aA[0][0]=fmaf(a0,v0.x,aA[0][0]); aA[0][1]=fmaf(a0,v0.y,aA[0][1]);
            aA[0][2]=fmaf(a0,v0.z,aA[0][2]); aA[0][3]=fmaf(a0,v0.w,aA[0][3]);
            aA[0][4]=fmaf(a0,v1.x,aA[0][4]); aA[0][5]=fmaf(a0,v1.y,aA[0][5]);
            aA[0][6]=fmaf(a0,v1.z,aA[0][6]); aA[0][7]=fmaf(a0,v1.w,aA[0][7]);
            aA[1][0]=fmaf(a1,v0.x,aA[1][0]); aA[1][1]=fmaf(a1,v0.y,aA[1][1]);
            aA[1][2]=fmaf(a1,v0.z,aA[1][2]); aA[1][3]=fmaf(a1,v0.w,aA[1][3]);
            aA[1][4]=fmaf(a1,v1.x,aA[1][4]); aA[1][5]=fmaf(a1,v1.y,aA[1][5]);
            aA[1][6]=fmaf(a1,v1.z,aA[1][6]); aA[1][7]=fmaf(a1,v1.w,aA[1][7]);
        }
        for (int d = 0; d < 64; d++) {
            float q0 = sQ[rr * 65 + d];
            float q1 = sQ[(rr + 1) * 65 + d];
            cqf0 = fmaf(q0, szf[d], cqf0);
            cqf1 = fmaf(q1, szf[d], cqf1);
            cqb0 = fmaf(q0, szb[d], cqb0);
            cqb1 = fmaf(q1, szb[d], cqb1);
            float4 f0 = *(const float4*)(sSf + d * 68 + c0);
            float4 f1 = *(const float4*)(sSf + d * 68 + c0 + 4);
            float4 b0 = *(const float4*)(sSb + d * 68 + c0);
            float4 b1 = *(const float4*)(sSb + d * 68 + c0 + 4);
            aIf[0][0]=fmaf(q0,f0.x,aIf[0][0]); aIf[0][1]=fmaf(q0,f0.y,aIf[0][1]);
            aIf[0][2]=fmaf(q0,f0.z,aIf[0][2]); aIf[0][3]=fmaf(q0,f0.w,aIf[0][3]);
            aIf[0][4]=fmaf(q0,f1.x,aIf[0][4]); aIf[0][5]=fmaf(q0,f1.y,aIf[0][5]);
            aIf[0][6]=fmaf(q0,f1.z,aIf[0][6]); aIf[0][7]=fmaf(q0,f1.w,aIf[0][7]);
            aIf[1][0]=fmaf(q1,f0.x,aIf[1][0]); aIf[1][1]=fmaf(q1,f0.y,aIf[1][1]);
            aIf[1][2]=fmaf(q1,f0.z,aIf[1][2]); aIf[1][3]=fmaf(q1,f0.w,aIf[1][3]);
            aIf[1][4]=fmaf(q1,f1.x,aIf[1][4]); aIf[1][5]=fmaf(q1,f1.y,aIf[1][5]);
            aIf[1][6]=fmaf(q1,f1.z,aIf[1][6]); aIf[1][7]=fmaf(q1,f1.w,aIf[1][7]);
            aIb[0][0]=fmaf(q0,b0.x,aIb[0][0]); aIb[0][1]=fmaf(q0,b0.y,aIb[0][1]);
            aIb[0][2]=fmaf(q0,b0.z,aIb[0][2]); aIb[0][3]=fmaf(q0,b0.w,aIb[0][3]);
            aIb[0][4]=fmaf(q0,b1.x,aIb[0][4]); aIb[0][5]=fmaf(q0,b1.y,aIb[0][5]);
            aIb[0][6]=fmaf(q0,b1.z,aIb[0][6]); aIb[0][7]=fmaf(q0,b1.w,aIb[0][7]);
            aIb[1][0]=fmaf(q1,b0.x,aIb[1][0]); aIb[1][1]=fmaf(q1,b0.y,aIb[1][1]);
            aIb[1][2]=fmaf(q1,b0.z,aIb[1][2]); aIb[1][3]=fmaf(q1,b0.w,aIb[1][3]);
            aIb[1][4]=fmaf(q1,b1.x,aIb[1][4]); aIb[1][5]=fmaf(q1,b1.y,aIb[1][5]);
            aIb[1][6]=fmaf(q1,b1.z,aIb[1][6]); aIb[1][7]=fmaf(q1,b1.w,aIb[1][7]);
        }

        int b = bh >> 3;
#pragma unroll
        for (int i = 0; i < 2; i++) {
            int r = rr + i;
            int t = j * CH_ + r;
            float lf = slp[r + 1];
            float lb = slp[CH_ - r];
            float cden = (i ? cs1 : cs0)
                       + lf * (i ? cqf1 : cqf0)
                       + lb * (i ? cqb1 : cqb0);
            float inv = 1.f / fmaxf(cden, 1e-6f);
            uint32_t hp[4];
#pragma unroll
            for (int u = 0; u < 4; u++){
                float y0 = (aA[i][2*u]   + lf*aIf[i][2*u]   + lb*aIb[i][2*u]  ) * inv;
                float y1 = (aA[i][2*u+1] + lf*aIf[i][2*u+1] + lb*aIb[i][2*u+1]) * inv;
                hp[u] = pack2(y0, y1);
            }
            size_t dst = ((size_t)(b * T_ + t) * D_) + h * HD_ + c0;
            *(uint4*)(g_ath + dst) = make_uint4(hp[0], hp[1], hp[2], hp[3]);
        }
    }
}

// ------------------------- launcher ----------------------------------------
extern "C" void kernel_launch(void* const* d_in, const int* in_sizes, int n_in,
                              void* d_out, int out_size)
{
    const float* x    = (const float*)d_in[0];
    const float* Wq   = (const float*)d_in[2];
    const float* Wk   = (const float*)d_in[3];
    const float* Wv   = (const float*)d_in[4];
    const float* Wo   = (const float*)d_in[5];
    const float* bo   = (const float*)d_in[6];
    const float* g1   = (const float*)d_in[7];
    const float* b1   = (const float*)d_in[8];
    const float* g2   = (const float*)d_in[9];
    const float* b2   = (const float*)d_in[10];
    const float* W1   = (const float*)d_in[11];
    const float* bf1  = (const float*)d_in[12];
    const float* W2   = (const float*)d_in[13];
    const float* bf2  = (const float*)d_in[14];
    const float* dlog = (const float*)d_in[15];
    float* out = (float*)d_out;

#define SYM(p, s) cudaGetSymbolAddress((void**)&p, s)
    __half *xnh,*ath,*h2h,*f1h;
    __half *wqkvh,*woh,*w1h,*w2h;
    float *x2;
    SYM(xnh,g_xnh); SYM(ath,g_ath); SYM(h2h,g_h2h); SYM(f1h,g_f1h);
    SYM(wqkvh,g_wqkvh); SYM(woh,g_woh); SYM(w1h,g_w1h); SYM(w2h,g_w2h);
    SYM(x2,g_x2);
#undef SYM

    cudaFuncSetAttribute(tc_gemm<4,512>,   cudaFuncAttributeMaxDynamicSharedMemorySize, GEMM_SMEM);
    cudaFuncSetAttribute(tc_gemm<3,512>,   cudaFuncAttributeMaxDynamicSharedMemorySize, GEMM_SMEM);
    cudaFuncSetAttribute(tc_gemm64<512>,   cudaFuncAttributeMaxDynamicSharedMemorySize, GEMM64_SMEM);
    cudaFuncSetAttribute(tc_gemm64<2048>,  cudaFuncAttributeMaxDynamicSharedMemorySize, GEMM64_SMEM);
    cudaFuncSetAttribute(chunk_comb_kernel,cudaFuncAttributeMaxDynamicSharedMemorySize, CC_SMEM_BYTES);

    dim3 blk(256);
    dim3 gQKV((3*D_) / 128, M_ / 128);  // (12, 32) = 384 CTAs
    dim3 gD64(D_ / 128, M_ / 64);       // (4, 64)  = 256 CTAs
    dim3 gF(F_ / 128, M_ / 128);        // (16, 32) = 512 CTAs

    // 0) all weight conversions, one launch
    split_all_kernel<<<786432/256, blk>>>(Wq, Wk, Wv, Wo, W1, W2);
    // 1) LN1 -> fp16
    ln_h_kernel<<<M_, blk>>>(x, g1, b1, xnh);
    // 2) fused Q/K/V projection (single-pass fp16, 3-stage) -> fp16 QKV
    tc_gemm<4,512><<<gQKV, blk, GEMM_SMEM>>>(xnh, wqkvh, 3*D_, nullptr, nullptr);
    // 3) dual-direction two-level scan + fused chunk/combine -> fp16 attn
    usum_dual_kernel<<<NBH_ * NCH_, blk>>>(dlog);
    sweep_kernel<<<2 * NBH_ * 16, blk>>>(dlog);
    chunk_comb_kernel<<<NBH_ * NCH_, blk, CC_SMEM_BYTES>>>(dlog);
    // 4) Wo + bias + residual -> fp32 x2
    tc_gemm64<512><<<gD64, blk, GEMM64_SMEM>>>(ath, woh, D_, bo, x, x2);
    // 5) LN2 -> fp16
    ln_h_kernel<<<M_, blk>>>(x2, g2, b2, h2h);
    // 6) FFN up + GELU -> fp16 (3-stage)
    tc_gemm<3,512><<<gF, blk, GEMM_SMEM>>>(h2h, w1h, F_, bf1, f1h);
    // 7) FFN down + bias + residual -> final output
    tc_gemm64<2048><<<gD64, blk, GEMM64_SMEM>>>(f1h, w2h, D_, bf2, x2, out);
}